// round 1
// baseline (speedup 1.0000x reference)
#include <cuda_runtime.h>
#include <math.h>

#define Bn 8
#define Cn 128
#define Hn 64
#define Wn 64
#define On 128
#define K2 9
#define HW 4096          // Hn*Wn
#define CK 1152          // Cn*K2

// ---------------- scratch (no allocations allowed) ----------------
__device__ float g_offmask[Bn * 27 * HW];      // [b][ch 0..26][pos]; ch<18 raw offsets, ch>=18 sigmoid(mask)
__device__ float g_wT[K2 * Cn * On];           // [j][c][o]  transposed weight

// ---------------- helpers: packed f32x2 ----------------
__device__ __forceinline__ void fma2(unsigned long long& d, unsigned long long a, unsigned long long b) {
    asm("fma.rn.f32x2 %0, %1, %2, %0;" : "+l"(d) : "l"(a), "l"(b));
}
__device__ __forceinline__ unsigned long long dup2(float v) {
    unsigned long long r;
    asm("mov.b64 %0, {%1, %1};" : "=l"(r) : "f"(v));
    return r;
}

// ---------------- kernel 0: weight transpose ----------------
__global__ void k_transpose_w(const float* __restrict__ w) {
    int i = blockIdx.x * 256 + threadIdx.x;
    if (i >= K2 * Cn * On) return;
    int o = i & 127;
    int c = (i >> 7) & 127;
    int j = i >> 14;
    g_wT[i] = w[o * CK + c * K2 + j];
}

// ---------------- kernel 1: offset + mask conv (27 out ch) ----------------
// block = 128 threads (16 rows x 8 col-pairs), tile 16x16 output, grid (4,4,8)
__global__ __launch_bounds__(128) void k_offmask(
    const float* __restrict__ x,
    const float* __restrict__ w_off, const float* __restrict__ b_off,
    const float* __restrict__ w_msk, const float* __restrict__ b_msk)
{
    __shared__ float xt[18][20];
    __shared__ float wt[243];

    const int b = blockIdx.z;
    const int ox0 = blockIdx.x * 16, oy0 = blockIdx.y * 16;
    const int t = threadIdx.x;
    const int ty = t >> 3, tx = t & 7;     // 2 horizontal pixels per thread

    float acc0[27], acc1[27];
#pragma unroll
    for (int oc = 0; oc < 27; oc++) { acc0[oc] = 0.f; acc1[oc] = 0.f; }

    const float* xb = x + (size_t)b * Cn * HW;

    for (int c = 0; c < Cn; c++) {
        // load 18x18 input tile (zero-padded)
        for (int e = t; e < 324; e += 128) {
            int yy = e / 18, xx = e - yy * 18;
            int gy = oy0 + yy - 1, gx = ox0 + xx - 1;
            float v = 0.f;
            if (gy >= 0 && gy < Hn && gx >= 0 && gx < Wn) v = xb[c * HW + gy * Wn + gx];
            xt[yy][xx] = v;
        }
        // load 27x9 weights for this channel
        for (int e = t; e < 243; e += 128) {
            int oc = e / 9, k = e - oc * 9;
            wt[e] = (oc < 18) ? w_off[oc * CK + c * K2 + k]
                              : w_msk[(oc - 18) * CK + c * K2 + k];
        }
        __syncthreads();

        float xv[3][4];
#pragma unroll
        for (int r = 0; r < 3; r++)
#pragma unroll
            for (int cc = 0; cc < 4; cc++) xv[r][cc] = xt[ty + r][2 * tx + cc];

#pragma unroll
        for (int oc = 0; oc < 27; oc++) {
#pragma unroll
            for (int ky = 0; ky < 3; ky++)
#pragma unroll
                for (int kx = 0; kx < 3; kx++) {
                    float wv = wt[oc * 9 + ky * 3 + kx];
                    acc0[oc] += wv * xv[ky][kx];
                    acc1[oc] += wv * xv[ky][kx + 1];
                }
        }
        __syncthreads();
    }

    const int gy = oy0 + ty, gx = ox0 + 2 * tx;
    const int p = gy * Wn + gx;
    float* om = g_offmask + (size_t)b * 27 * HW;
#pragma unroll
    for (int oc = 0; oc < 18; oc++) {
        float bb = b_off[oc];
        om[oc * HW + p]     = acc0[oc] + bb;
        om[oc * HW + p + 1] = acc1[oc] + bb;
    }
#pragma unroll
    for (int oc = 18; oc < 27; oc++) {
        float bb = b_msk[oc - 18];
        float z0 = acc0[oc] + bb, z1 = acc1[oc] + bb;
        om[oc * HW + p]     = 1.f / (1.f + __expf(-z0));
        om[oc * HW + p + 1] = 1.f / (1.f + __expf(-z1));
    }
}

// ---------------- kernel 2: deformable gather + implicit GEMM ----------------
// One CTA = one (b, ho) row: 64 positions x 128 output channels, reduce over 1152.
// Thread tile: 8 o (packed as 4 o-pairs) x 4 positions. 256 threads.
#define CCH 16
__global__ __launch_bounds__(256) void k_main(
    const float* __restrict__ x, float* __restrict__ out)
{
    extern __shared__ float smem[];
    float* w_s   = smem;                         // 16384 floats: [c][o] for current j
    float* val_s = smem + 16384;                 // CCH*64
    int*   tap_i = (int*)(smem + 16384 + CCH * 64);   // [4][64]
    float* tap_w = smem + 16384 + CCH * 64 + 256;     // [4][64]

    const int bh = blockIdx.x;
    const int b = bh >> 6, ho = bh & 63;
    const int t = threadIdx.x;
    const int og = t >> 4;       // 0..15 -> o = og*8 .. og*8+7
    const int pg = t & 15;       // 0..15 -> pos = pg*4 .. pg*4+3

    unsigned long long acc[4][4];
#pragma unroll
    for (int i = 0; i < 4; i++)
#pragma unroll
        for (int jj = 0; jj < 4; jj++) acc[i][jj] = 0ull;

    const float* xb = x + (size_t)b * Cn * HW;
    const float* om = g_offmask + (size_t)b * 27 * HW;

    for (int j = 0; j < K2; j++) {
        // --- per-position bilinear taps (threads 0..63) ---
        if (t < 64) {
            int wo = t;
            int p = ho * Wn + wo;
            float dy = om[(2 * j) * HW + p];
            float dx = om[(2 * j + 1) * HW + p];
            float m  = om[(18 + j) * HW + p];
            float py = dy + (float)(j / 3) + (float)ho - 1.f;
            float px = dx + (float)(j % 3) + (float)wo - 1.f;
            float y0f = floorf(py), x0f = floorf(px);
            float ly = py - y0f, lx = px - x0f;
            int y0 = (int)y0f, x0 = (int)x0f;
#pragma unroll
            for (int tt = 0; tt < 4; tt++) {
                int yy = y0 + (tt >> 1);
                int xx = x0 + (tt & 1);
                bool valid = (yy >= 0) && (yy < Hn) && (xx >= 0) && (xx < Wn);
                int yc = min(max(yy, 0), Hn - 1);
                int xc = min(max(xx, 0), Wn - 1);
                tap_i[tt * 64 + wo] = yc * Wn + xc;
                float wy = (tt >> 1) ? ly : (1.f - ly);
                float wx = (tt & 1) ? lx : (1.f - lx);
                tap_w[tt * 64 + wo] = valid ? (wy * wx * m) : 0.f;
            }
        }
        // --- load weights for this j: [128 c][128 o] = 64KB, coalesced float4 ---
        {
            const float4* src = (const float4*)(g_wT + j * (Cn * On));
            float4* dst = (float4*)w_s;
#pragma unroll
            for (int e = t; e < (Cn * On) / 4; e += 256) dst[e] = src[e];
        }
        __syncthreads();

        for (int c0 = 0; c0 < Cn; c0 += CCH) {
            // --- gather + bilinear: val_s[cc][wo], 1024 entries, 4 per thread ---
#pragma unroll
            for (int r = 0; r < 4; r++) {
                int e = t + r * 256;
                int cc = e >> 6, wo = e & 63;
                const float* xc = xb + (size_t)(c0 + cc) * HW;
                float v = tap_w[0 * 64 + wo] * __ldg(&xc[tap_i[0 * 64 + wo]])
                        + tap_w[1 * 64 + wo] * __ldg(&xc[tap_i[1 * 64 + wo]])
                        + tap_w[2 * 64 + wo] * __ldg(&xc[tap_i[2 * 64 + wo]])
                        + tap_w[3 * 64 + wo] * __ldg(&xc[tap_i[3 * 64 + wo]]);
                val_s[cc * 64 + wo] = v;
            }
            __syncthreads();

            // --- packed f32x2 GEMM micro-kernel ---
#pragma unroll
            for (int cc = 0; cc < CCH; cc++) {
                const unsigned long long* wrow =
                    (const unsigned long long*)(w_s + (c0 + cc) * On + og * 8);
                unsigned long long w2[4];
#pragma unroll
                for (int i = 0; i < 4; i++) w2[i] = wrow[i];
                float4 v4 = *(const float4*)(val_s + cc * 64 + pg * 4);
                unsigned long long vv[4];
                vv[0] = dup2(v4.x); vv[1] = dup2(v4.y);
                vv[2] = dup2(v4.z); vv[3] = dup2(v4.w);
#pragma unroll
                for (int i = 0; i < 4; i++)
#pragma unroll
                    for (int jj = 0; jj < 4; jj++) fma2(acc[i][jj], w2[i], vv[jj]);
            }
            __syncthreads();
        }
    }

    // --- stage results in smem (reuse w_s), then coalesced float4 stores ---
    union U { unsigned long long u; float2 f; };
#pragma unroll
    for (int i = 0; i < 4; i++) {
        int o = og * 8 + 2 * i;
#pragma unroll
        for (int jj = 0; jj < 4; jj++) {
            U u; u.u = acc[i][jj];
            int wo = pg * 4 + jj;
            w_s[o * 64 + wo]       = u.f.x;
            w_s[(o + 1) * 64 + wo] = u.f.y;
        }
    }
    __syncthreads();

    float* ob = out + (size_t)b * On * HW + ho * Wn;
    const float4* st4 = (const float4*)w_s;
#pragma unroll
    for (int e = t; e < (On * 64) / 4; e += 256) {
        int o = e >> 4;
        int q = e & 15;
        ((float4*)(ob + (size_t)o * HW))[q] = st4[e];
    }
}

// ---------------- launch ----------------
extern "C" void kernel_launch(void* const* d_in, const int* in_sizes, int n_in,
                              void* d_out, int out_size) {
    const float* x      = (const float*)d_in[0];
    const float* w_off  = (const float*)d_in[1];
    const float* b_off  = (const float*)d_in[2];
    const float* w_msk  = (const float*)d_in[3];
    const float* b_msk  = (const float*)d_in[4];
    const float* weight = (const float*)d_in[5];
    float* out = (float*)d_out;

    // kernel 0: transpose weight -> [j][c][o]
    k_transpose_w<<<(K2 * Cn * On + 255) / 256, 256>>>(weight);

    // kernel 1: offset + mask convs
    dim3 g1(4, 4, Bn);
    k_offmask<<<g1, 128>>>(x, w_off, b_off, w_msk, b_msk);

    // kernel 2: deformable gather + GEMM
    const int smem_bytes = (16384 + CCH * 64 + 256 + 256) * 4;
    cudaFuncSetAttribute(k_main, cudaFuncAttributeMaxDynamicSharedMemorySize, smem_bytes);
    k_main<<<Bn * Hn, 256, smem_bytes>>>(x, out);
}

// round 3
// speedup vs baseline: 1.3848x; 1.3848x over previous
#include <cuda_runtime.h>
#include <cuda_bf16.h>
#include <cstdint>
#include <math.h>

#define Bn 8
#define Cn 128
#define Hn 64
#define Wn 64
#define On 128
#define K2 9
#define HW 4096
#define CK 1152
#define NCH 18          // 9 j * 2 channel-halves (K-chunks of 64)

// ---------------- scratch ----------------
__device__ float g_offmask[Bn * 27 * HW];              // [b][ch 0..26][pos]
__device__ float g_xt[Bn * HW * Cn];                   // NHWC transpose of x
// A fragments, bf16 hi/lo in per-lane mma order:
// main: [it18][mw4][mt2][kt4][term2][lane32][16B]
__device__ __align__(16) unsigned char g_Amain[NCH * 32768];
// off:  [it18][mt2][kt4][term2][lane32][16B]
__device__ __align__(16) unsigned char g_Aoff[NCH * 8192];

// ---------------- helpers ----------------
__device__ __forceinline__ uint32_t pack_bf16x2(float hi, float lo) {
    uint32_t r;
    asm("cvt.rn.bf16x2.f32 %0, %1, %2;" : "=r"(r) : "f"(hi), "f"(lo));
    return r;
}
// split fp32 pair (v0=lower lane, v1=upper) into bf16x2 hi + lo remainder
__device__ __forceinline__ void split2(float v0, float v1, uint32_t& hp, uint32_t& lp) {
    hp = pack_bf16x2(v1, v0);
    float h0 = __uint_as_float(hp << 16);
    float h1 = __uint_as_float(hp & 0xffff0000u);
    lp = pack_bf16x2(v1 - h1, v0 - h0);
}
__device__ __forceinline__ void mma_bf16(float* d, const uint32_t* a, uint32_t b0, uint32_t b1) {
    asm volatile(
        "mma.sync.aligned.m16n8k16.row.col.f32.bf16.bf16.f32 "
        "{%0,%1,%2,%3},{%4,%5,%6,%7},{%8,%9},{%0,%1,%2,%3};"
        : "+f"(d[0]), "+f"(d[1]), "+f"(d[2]), "+f"(d[3])
        : "r"(a[0]), "r"(a[1]), "r"(a[2]), "r"(a[3]), "r"(b0), "r"(b1));
}

// ---------------- kernel: NCHW -> NHWC transpose ----------------
__global__ __launch_bounds__(256) void k_xt(const float* __restrict__ x) {
    __shared__ float sm[32][33];
    const int tx = threadIdx.x, ty = threadIdx.y;
    const int hw0 = blockIdx.x * 32, c0 = blockIdx.y * 32, b = blockIdx.z;
    const float* xb = x + (size_t)b * Cn * HW;
    float* xtb = g_xt + (size_t)b * HW * Cn;
#pragma unroll
    for (int i = 0; i < 4; i++) {
        int c = c0 + ty + i * 8;
        sm[ty + i * 8][tx] = xb[(size_t)c * HW + hw0 + tx];
    }
    __syncthreads();
#pragma unroll
    for (int i = 0; i < 4; i++) {
        int hw = hw0 + ty + i * 8;
        xtb[(size_t)hw * Cn + c0 + tx] = sm[tx][ty + i * 8];
    }
}

// ---------------- kernel: weight prep into mma A-fragment order ----------------
__global__ void k_prep(const float* __restrict__ wmain,
                       const float* __restrict__ woff,
                       const float* __restrict__ wmsk) {
    int i = blockIdx.x * 256 + threadIdx.x;
    if (i < 18432) {
        // main: i = ((((it*4)+mw)*2+mt)*4+kt)*32 + lane
        int lane = i & 31, kt = (i >> 5) & 3, mt = (i >> 7) & 1, mw = (i >> 8) & 3, it = i >> 10;
        int gid = lane >> 2, tig = lane & 3;
        int j = it >> 1, ch = it & 1;
        int r0 = mw * 32 + mt * 16 + gid;
        int cb = ch * 64 + kt * 16 + tig * 2;     // global c of first col
        float w[2][4];
#pragma unroll
        for (int rr = 0; rr < 2; rr++) {
            int r = r0 + rr * 8;
#pragma unroll
            for (int cc = 0; cc < 4; cc++) {
                int c = cb + (cc >> 1) * 8 + (cc & 1);
                w[rr][cc] = wmain[(size_t)r * CK + c * K2 + j];
            }
        }
        uint4 hi, lo;
        uint32_t hp, lp;
        split2(w[0][0], w[0][1], hp, lp); hi.x = hp; lo.x = lp;
        split2(w[1][0], w[1][1], hp, lp); hi.y = hp; lo.y = lp;
        split2(w[0][2], w[0][3], hp, lp); hi.z = hp; lo.z = lp;
        split2(w[1][2], w[1][3], hp, lp); hi.w = hp; lo.w = lp;
        size_t base = (size_t)it * 32768 + ((((mw * 2 + mt) * 4 + kt) * 2) * 32 + lane) * 16;
        *(uint4*)(g_Amain + base) = hi;
        *(uint4*)(g_Amain + base + 512) = lo;
    } else if (i < 18432 + 4608) {
        int q = i - 18432;
        int lane = q & 31, kt = (q >> 5) & 3, mt = (q >> 7) & 1, it = q >> 8;
        int gid = lane >> 2, tig = lane & 3;
        int j = it >> 1, ch = it & 1;
        int r0 = mt * 16 + gid;
        int cb = ch * 64 + kt * 16 + tig * 2;
        float w[2][4];
#pragma unroll
        for (int rr = 0; rr < 2; rr++) {
            int r = r0 + rr * 8;
#pragma unroll
            for (int cc = 0; cc < 4; cc++) {
                int c = cb + (cc >> 1) * 8 + (cc & 1);
                float v = 0.f;
                if (r < 18)      v = woff[(size_t)r * CK + c * K2 + j];
                else if (r < 27) v = wmsk[(size_t)(r - 18) * CK + c * K2 + j];
                w[rr][cc] = v;
            }
        }
        uint4 hi, lo;
        uint32_t hp, lp;
        split2(w[0][0], w[0][1], hp, lp); hi.x = hp; lo.x = lp;
        split2(w[1][0], w[1][1], hp, lp); hi.y = hp; lo.y = lp;
        split2(w[0][2], w[0][3], hp, lp); hi.z = hp; lo.z = lp;
        split2(w[1][2], w[1][3], hp, lp); hi.w = hp; lo.w = lp;
        size_t base = (size_t)it * 8192 + (((mt * 4 + kt) * 2) * 32 + lane) * 16;
        *(uint4*)(g_Aoff + base) = hi;
        *(uint4*)(g_Aoff + base + 512) = lo;
    }
}

// ---------------- kernel: offset+mask conv (M=32 HMMA GEMM) ----------------
// CTA: 256 thr = 8 warps, each warp N=16 (2 ntiles), M=32. CTA covers 128 pos (2 rows).
__global__ __launch_bounds__(256) void k_offmask_mma(
    const float* __restrict__ b_off, const float* __restrict__ b_msk)
{
    const int t = threadIdx.x, wid = t >> 5, lane = t & 31;
    const int gid = lane >> 2, tig = lane & 3;
    const int b = blockIdx.x >> 5, rp = blockIdx.x & 31, ho0 = rp * 2;
    const float* xtb = g_xt + (size_t)b * HW * Cn;

    float acc[2][2][4];
#pragma unroll
    for (int mt = 0; mt < 2; mt++)
#pragma unroll
        for (int nt = 0; nt < 2; nt++)
#pragma unroll
            for (int r = 0; r < 4; r++) acc[mt][nt][r] = 0.f;

    for (int it = 0; it < NCH; it++) {
        const int j = it >> 1, ch = it & 1;
        const int jy = j / 3, jx = j - jy * 3;
        // A fragments (2 mt x 4 kt x 2 terms)
        uint32_t aH[2][4][4], aL[2][4][4];
        {
            const unsigned char* gb = g_Aoff + (size_t)it * 8192 + lane * 16;
#pragma unroll
            for (int mt = 0; mt < 2; mt++)
#pragma unroll
                for (int kt = 0; kt < 4; kt++) {
                    size_t o = ((mt * 4 + kt) * 2) * 512;
                    *(uint4*)aH[mt][kt] = *(const uint4*)(gb + o);
                    *(uint4*)aL[mt][kt] = *(const uint4*)(gb + o + 512);
                }
        }
#pragma unroll
        for (int nt = 0; nt < 2; nt++) {
            int pos = wid * 16 + nt * 8 + gid;
            int row = ho0 + (pos >> 6), col = pos & 63;
            int sy = row + jy - 1, sx = col + jx - 1;
            bool valid = ((unsigned)sy < Hn) && ((unsigned)sx < Wn);
            const float* src = xtb + ((size_t)(valid ? sy * Wn + sx : 0)) * Cn + ch * 64 + tig * 2;
#pragma unroll
            for (int kt = 0; kt < 4; kt++) {
                float2 p0 = make_float2(0.f, 0.f), p1 = p0;
                if (valid) {
                    p0 = *(const float2*)(src + kt * 16);
                    p1 = *(const float2*)(src + kt * 16 + 8);
                }
                uint32_t b0h, b0l, b1h, b1l;
                split2(p0.x, p0.y, b0h, b0l);
                split2(p1.x, p1.y, b1h, b1l);
#pragma unroll
                for (int mt = 0; mt < 2; mt++) {
                    mma_bf16(acc[mt][nt], aH[mt][kt], b0h, b1h);
                    mma_bf16(acc[mt][nt], aH[mt][kt], b0l, b1l);
                    mma_bf16(acc[mt][nt], aL[mt][kt], b0h, b1h);
                }
            }
        }
    }
    // epilogue: bias (+sigmoid for mask rows), write g_offmask
    float* om = g_offmask + (size_t)b * 27 * HW;
#pragma unroll
    for (int mt = 0; mt < 2; mt++)
#pragma unroll
        for (int rr = 0; rr < 2; rr++) {
            int o = mt * 16 + gid + rr * 8;
            if (o >= 27) continue;
            float bias = (o < 18) ? __ldg(b_off + o) : __ldg(b_msk + o - 18);
#pragma unroll
            for (int nt = 0; nt < 2; nt++) {
                int pos = wid * 16 + nt * 8 + 2 * tig;
                int gp = (ho0 + (pos >> 6)) * Wn + (pos & 63);
                float v0 = acc[mt][nt][rr * 2 + 0] + bias;
                float v1 = acc[mt][nt][rr * 2 + 1] + bias;
                if (o >= 18) {
                    v0 = 1.f / (1.f + __expf(-v0));
                    v1 = 1.f / (1.f + __expf(-v1));
                }
                *(float2*)(om + (size_t)o * HW + gp) = make_float2(v0, v1);
            }
        }
}

// ---------------- kernel: deformable gather + HMMA GEMM ----------------
// CTA: 256 thr = 8 warps (mw 0..3 x nw 0..1). Warp tile: M=32, N=64.
// CTA covers 128 positions (rows ho0, ho0+1), all 128 output channels.
__global__ __launch_bounds__(256) void k_main_mma(float* __restrict__ out)
{
    extern __shared__ __align__(16) char smem[];
    const int t = threadIdx.x, wid = t >> 5, lane = t & 31;
    const int gid = lane >> 2, tig = lane & 3;
    const int mw = wid >> 1, nw = wid & 1;
    const int b = blockIdx.x >> 5, rp = blockIdx.x & 31, ho0 = rp * 2;
    const float* xtb = g_xt + (size_t)b * HW * Cn;
    const float* om = g_offmask + (size_t)b * 27 * HW;

    // per-warp tap storage: [wid][64 pos][ i0..3 | w0..3 ] (32B per pos)
    char* tap_base = smem + wid * 64 * 32;

    float acc[2][8][4];
#pragma unroll
    for (int mt = 0; mt < 2; mt++)
#pragma unroll
        for (int nt = 0; nt < 8; nt++)
#pragma unroll
            for (int r = 0; r < 4; r++) acc[mt][nt][r] = 0.f;

    const int myrow = ho0 + nw;

    for (int it = 0; it < NCH; it++) {
        const int j = it >> 1, ch = it & 1;
        if (ch == 0) {
            // compute taps for this warp's 64 positions (2 per lane)
            const int jy = j / 3, jx = j - jy * 3;
#pragma unroll
            for (int h = 0; h < 2; h++) {
                int pp = lane + h * 32;
                int gp = myrow * Wn + pp;
                float dy = __ldg(om + (size_t)(2 * j) * HW + gp);
                float dx = __ldg(om + (size_t)(2 * j + 1) * HW + gp);
                float m  = __ldg(om + (size_t)(18 + j) * HW + gp);
                float py = dy + (float)(jy + myrow - 1);
                float px = dx + (float)(jx + pp - 1);
                float y0f = floorf(py), x0f = floorf(px);
                float ly = py - y0f, lx = px - x0f;
                int y0 = (int)y0f, x0 = (int)x0f;
                int4 ti; float4 tw;
                {
                    int yy = y0, xx = x0;
                    bool v = (yy >= 0) && (yy < Hn) && (xx >= 0) && (xx < Wn);
                    ti.x = min(max(yy, 0), Hn - 1) * Wn + min(max(xx, 0), Wn - 1);
                    tw.x = v ? (1.f - ly) * (1.f - lx) * m : 0.f;
                }
                {
                    int yy = y0, xx = x0 + 1;
                    bool v = (yy >= 0) && (yy < Hn) && (xx >= 0) && (xx < Wn);
                    ti.y = min(max(yy, 0), Hn - 1) * Wn + min(max(xx, 0), Wn - 1);
                    tw.y = v ? (1.f - ly) * lx * m : 0.f;
                }
                {
                    int yy = y0 + 1, xx = x0;
                    bool v = (yy >= 0) && (yy < Hn) && (xx >= 0) && (xx < Wn);
                    ti.z = min(max(yy, 0), Hn - 1) * Wn + min(max(xx, 0), Wn - 1);
                    tw.z = v ? ly * (1.f - lx) * m : 0.f;
                }
                {
                    int yy = y0 + 1, xx = x0 + 1;
                    bool v = (yy >= 0) && (yy < Hn) && (xx >= 0) && (xx < Wn);
                    ti.w = min(max(yy, 0), Hn - 1) * Wn + min(max(xx, 0), Wn - 1);
                    tw.w = v ? ly * lx * m : 0.f;
                }
                *(int4*)(tap_base + pp * 32) = ti;
                *(float4*)(tap_base + pp * 32 + 16) = tw;
            }
            __syncwarp();
        }
        // A fragments
        uint32_t aH[2][4][4], aL[2][4][4];
        {
            const unsigned char* gb = g_Amain + (size_t)it * 32768 + (size_t)mw * 8192 + lane * 16;
#pragma unroll
            for (int mt = 0; mt < 2; mt++)
#pragma unroll
                for (int kt = 0; kt < 4; kt++) {
                    size_t o = ((mt * 4 + kt) * 2) * 512;
                    *(uint4*)aH[mt][kt] = *(const uint4*)(gb + o);
                    *(uint4*)aL[mt][kt] = *(const uint4*)(gb + o + 512);
                }
        }
#pragma unroll
        for (int nt = 0; nt < 8; nt++) {
            int pos = nt * 8 + gid;
            int4 ti = *(const int4*)(tap_base + pos * 32);
            float4 tw = *(const float4*)(tap_base + pos * 32 + 16);
            const float* s0 = xtb + (size_t)ti.x * Cn + ch * 64 + tig * 2;
            const float* s1 = xtb + (size_t)ti.y * Cn + ch * 64 + tig * 2;
            const float* s2 = xtb + (size_t)ti.z * Cn + ch * 64 + tig * 2;
            const float* s3 = xtb + (size_t)ti.w * Cn + ch * 64 + tig * 2;
#pragma unroll
            for (int kt = 0; kt < 4; kt++) {
                float2 g0 = *(const float2*)(s0 + kt * 16);
                float2 g1 = *(const float2*)(s1 + kt * 16);
                float2 g2 = *(const float2*)(s2 + kt * 16);
                float2 g3 = *(const float2*)(s3 + kt * 16);
                float2 h0 = *(const float2*)(s0 + kt * 16 + 8);
                float2 h1 = *(const float2*)(s1 + kt * 16 + 8);
                float2 h2 = *(const float2*)(s2 + kt * 16 + 8);
                float2 h3 = *(const float2*)(s3 + kt * 16 + 8);
                float v0 = fmaf(tw.x, g0.x, fmaf(tw.y, g1.x, fmaf(tw.z, g2.x, tw.w * g3.x)));
                float v1 = fmaf(tw.x, g0.y, fmaf(tw.y, g1.y, fmaf(tw.z, g2.y, tw.w * g3.y)));
                float v2 = fmaf(tw.x, h0.x, fmaf(tw.y, h1.x, fmaf(tw.z, h2.x, tw.w * h3.x)));
                float v3 = fmaf(tw.x, h0.y, fmaf(tw.y, h1.y, fmaf(tw.z, h2.y, tw.w * h3.y)));
                uint32_t b0h, b0l, b1h, b1l;
                split2(v0, v1, b0h, b0l);
                split2(v2, v3, b1h, b1l);
#pragma unroll
                for (int mt = 0; mt < 2; mt++) {
                    mma_bf16(acc[mt][nt], aH[mt][kt], b0h, b1h);
                    mma_bf16(acc[mt][nt], aH[mt][kt], b0l, b1l);
                    mma_bf16(acc[mt][nt], aL[mt][kt], b0h, b1h);
                }
            }
        }
    }

    // epilogue: stage to smem [128 o][132 pad], then coalesced float4 stores
    __syncthreads();
    float* stage = (float*)smem;
#pragma unroll
    for (int mt = 0; mt < 2; mt++) {
        int r0 = mw * 32 + mt * 16 + gid;
#pragma unroll
        for (int nt = 0; nt < 8; nt++) {
            int pos0 = nw * 64 + nt * 8 + 2 * tig;
            *(float2*)(stage + r0 * 132 + pos0) = make_float2(acc[mt][nt][0], acc[mt][nt][1]);
            *(float2*)(stage + (r0 + 8) * 132 + pos0) = make_float2(acc[mt][nt][2], acc[mt][nt][3]);
        }
    }
    __syncthreads();
    float* ob = out + (size_t)b * On * HW + (size_t)ho0 * Wn;
#pragma unroll
    for (int e = t; e < 4096; e += 256) {
        int o = e >> 5, p4 = e & 31;
        float4 v = *(float4*)(stage + o * 132 + p4 * 4);
        *(float4*)(ob + (size_t)o * HW + p4 * 4) = v;
    }
}

// ---------------- launch ----------------
extern "C" void kernel_launch(void* const* d_in, const int* in_sizes, int n_in,
                              void* d_out, int out_size) {
    const float* x      = (const float*)d_in[0];
    const float* w_off  = (const float*)d_in[1];
    const float* b_off  = (const float*)d_in[2];
    const float* w_msk  = (const float*)d_in[3];
    const float* b_msk  = (const float*)d_in[4];
    const float* weight = (const float*)d_in[5];
    float* out = (float*)d_out;

    dim3 gxt(HW / 32, Cn / 32, Bn);
    k_xt<<<gxt, dim3(32, 8)>>>(x);
    k_prep<<<(18432 + 4608 + 255) / 256, 256>>>(weight, w_off, w_msk);
    k_offmask_mma<<<Bn * 32, 256>>>(b_off, b_msk);

    const int smem_bytes = 128 * 132 * 4;   // 67584 (>= tap region 64KB... taps use 64KB? taps = 8*64*32 = 16KB, stage 67.6KB)
    cudaFuncSetAttribute(k_main_mma, cudaFuncAttributeMaxDynamicSharedMemorySize, smem_bytes);
    k_main_mma<<<Bn * 32, 256, smem_bytes>>>(out);
}

// round 4
// speedup vs baseline: 2.9327x; 2.1179x over previous
#include <cuda_runtime.h>
#include <cuda_bf16.h>
#include <cuda_fp16.h>
#include <cstdint>
#include <math.h>

#define Bn 8
#define Cn 128
#define Hn 64
#define Wn 64
#define On 128
#define K2 9
#define HW 4096
#define CK 1152
#define NCH 18          // 9 j * 2 channel-halves (K-chunks of 64)

// ---------------- scratch ----------------
__device__ float g_offmask[Bn * 27 * HW];              // [b][ch 0..26][pos]
__device__ __half g_xt[Bn * HW * Cn];                  // NHWC fp16 copy of x
// main A frags: [it18][w8][kt4][term2][lane32][16B]  (M=16 per warp)
__device__ __align__(16) unsigned char g_Amain[NCH * 32768];
// off A frags:  [it18][mt2][kt4][term2][lane32][16B]
__device__ __align__(16) unsigned char g_Aoff[NCH * 8192];

// smem layout for k_main (bytes)
#define SMB(s)    ((s) * 36864)     // B stage: 128 pos x 288B (32 cp x 8B + pad)
#define SM_TAPS   73728             // 8 warps x 512B
#define SM_TOTAL  77824

// ---------------- helpers ----------------
__device__ __forceinline__ uint32_t pack_bf16x2(float hi, float lo) {
    uint32_t r;
    asm("cvt.rn.bf16x2.f32 %0, %1, %2;" : "=r"(r) : "f"(hi), "f"(lo));
    return r;
}
__device__ __forceinline__ void split2(float v0, float v1, uint32_t& hp, uint32_t& lp) {
    hp = pack_bf16x2(v1, v0);
    float h0 = __uint_as_float(hp << 16);
    float h1 = __uint_as_float(hp & 0xffff0000u);
    lp = pack_bf16x2(v1 - h1, v0 - h0);
}
__device__ __forceinline__ void mma_bf16(float* d, const uint32_t* a, uint32_t b0, uint32_t b1) {
    asm volatile(
        "mma.sync.aligned.m16n8k16.row.col.f32.bf16.bf16.f32 "
        "{%0,%1,%2,%3},{%4,%5,%6,%7},{%8,%9},{%0,%1,%2,%3};"
        : "+f"(d[0]), "+f"(d[1]), "+f"(d[2]), "+f"(d[3])
        : "r"(a[0]), "r"(a[1]), "r"(a[2]), "r"(a[3]), "r"(b0), "r"(b1));
}

// ---------------- kernel: NCHW fp32 -> NHWC fp16 ----------------
__global__ __launch_bounds__(256) void k_xt(const float* __restrict__ x) {
    __shared__ float sm[32][33];
    const int tx = threadIdx.x, ty = threadIdx.y;
    const int hw0 = blockIdx.x * 32, c0 = blockIdx.y * 32, b = blockIdx.z;
    const float* xb = x + (size_t)b * Cn * HW;
    __half* xtb = g_xt + (size_t)b * HW * Cn;
#pragma unroll
    for (int i = 0; i < 4; i++)
        sm[ty + i * 8][tx] = xb[(size_t)(c0 + ty + i * 8) * HW + hw0 + tx];
    __syncthreads();
    const int id = ty * 32 + tx;
#pragma unroll
    for (int r = 0; r < 2; r++) {
        int item = id + r * 256;
        int hwl = item >> 4, cp = item & 15;
        __half2 h = __floats2half2_rn(sm[cp * 2][hwl], sm[cp * 2 + 1][hwl]);
        *(__half2*)(xtb + (size_t)(hw0 + hwl) * Cn + c0 + cp * 2) = h;
    }
}

// ---------------- kernel: weight prep ----------------
__global__ void k_prep(const float* __restrict__ wmain,
                       const float* __restrict__ woff,
                       const float* __restrict__ wmsk) {
    int i = blockIdx.x * 256 + threadIdx.x;
    if (i < 18432) {
        // [it][w][kt][lane]
        int lane = i & 31, kt = (i >> 5) & 3, w = (i >> 7) & 7, it = i >> 10;
        int gid = lane >> 2, tig = lane & 3;
        int j = it >> 1, ch = it & 1;
        int r0 = w * 16 + gid;
        int cb = ch * 64 + kt * 16 + tig * 2;
        float wv[2][4];
#pragma unroll
        for (int rr = 0; rr < 2; rr++) {
            int r = r0 + rr * 8;
#pragma unroll
            for (int cc = 0; cc < 4; cc++) {
                int c = cb + (cc >> 1) * 8 + (cc & 1);
                wv[rr][cc] = wmain[(size_t)r * CK + c * K2 + j];
            }
        }
        uint4 hi, lo; uint32_t hp, lp;
        split2(wv[0][0], wv[0][1], hp, lp); hi.x = hp; lo.x = lp;
        split2(wv[1][0], wv[1][1], hp, lp); hi.y = hp; lo.y = lp;
        split2(wv[0][2], wv[0][3], hp, lp); hi.z = hp; lo.z = lp;
        split2(wv[1][2], wv[1][3], hp, lp); hi.w = hp; lo.w = lp;
        size_t base = (size_t)it * 32768 + (size_t)((w * 4 + kt) * 2) * 512 + lane * 16;
        *(uint4*)(g_Amain + base) = hi;
        *(uint4*)(g_Amain + base + 512) = lo;
    } else if (i < 18432 + 4608) {
        int q = i - 18432;
        int lane = q & 31, kt = (q >> 5) & 3, mt = (q >> 7) & 1, it = q >> 8;
        int gid = lane >> 2, tig = lane & 3;
        int j = it >> 1, ch = it & 1;
        int r0 = mt * 16 + gid;
        int cb = ch * 64 + kt * 16 + tig * 2;
        float wv[2][4];
#pragma unroll
        for (int rr = 0; rr < 2; rr++) {
            int r = r0 + rr * 8;
#pragma unroll
            for (int cc = 0; cc < 4; cc++) {
                int c = cb + (cc >> 1) * 8 + (cc & 1);
                float v = 0.f;
                if (r < 18)      v = woff[(size_t)r * CK + c * K2 + j];
                else if (r < 27) v = wmsk[(size_t)(r - 18) * CK + c * K2 + j];
                wv[rr][cc] = v;
            }
        }
        uint4 hi, lo; uint32_t hp, lp;
        split2(wv[0][0], wv[0][1], hp, lp); hi.x = hp; lo.x = lp;
        split2(wv[1][0], wv[1][1], hp, lp); hi.y = hp; lo.y = lp;
        split2(wv[0][2], wv[0][3], hp, lp); hi.z = hp; lo.z = lp;
        split2(wv[1][2], wv[1][3], hp, lp); hi.w = hp; lo.w = lp;
        size_t base = (size_t)it * 8192 + (size_t)(((mt * 4 + kt) * 2) * 32 + lane) * 16;
        *(uint4*)(g_Aoff + base) = hi;
        *(uint4*)(g_Aoff + base + 512) = lo;
    }
}

// ---------------- kernel: offset+mask conv (M=32 HMMA GEMM) ----------------
__global__ __launch_bounds__(256) void k_offmask_mma(
    const float* __restrict__ b_off, const float* __restrict__ b_msk)
{
    const int t = threadIdx.x, wid = t >> 5, lane = t & 31;
    const int gid = lane >> 2, tig = lane & 3;
    const int b = blockIdx.x >> 5, rp = blockIdx.x & 31, ho0 = rp * 2;
    const __half* xtb = g_xt + (size_t)b * HW * Cn;

    float acc[2][2][4];
#pragma unroll
    for (int mt = 0; mt < 2; mt++)
#pragma unroll
        for (int nt = 0; nt < 2; nt++)
#pragma unroll
            for (int r = 0; r < 4; r++) acc[mt][nt][r] = 0.f;

    for (int it = 0; it < NCH; it++) {
        const int j = it >> 1, ch = it & 1;
        const int jy = j / 3, jx = j - jy * 3;
        uint32_t aH[2][4][4], aL[2][4][4];
        {
            const unsigned char* gb = g_Aoff + (size_t)it * 8192 + lane * 16;
#pragma unroll
            for (int mt = 0; mt < 2; mt++)
#pragma unroll
                for (int kt = 0; kt < 4; kt++) {
                    size_t o = (size_t)((mt * 4 + kt) * 2) * 512;
                    *(uint4*)aH[mt][kt] = *(const uint4*)(gb + o);
                    *(uint4*)aL[mt][kt] = *(const uint4*)(gb + o + 512);
                }
        }
#pragma unroll
        for (int nt = 0; nt < 2; nt++) {
            int pos = wid * 16 + nt * 8 + gid;
            int row = ho0 + (pos >> 6), col = pos & 63;
            int sy = row + jy - 1, sx = col + jx - 1;
            bool valid = ((unsigned)sy < Hn) && ((unsigned)sx < Wn);
            const __half* src = xtb + (size_t)(valid ? sy * Wn + sx : 0) * Cn + ch * 64 + tig * 2;
#pragma unroll
            for (int kt = 0; kt < 4; kt++) {
                float2 p0 = make_float2(0.f, 0.f), p1 = p0;
                if (valid) {
                    p0 = __half22float2(*(const __half2*)(src + kt * 16));
                    p1 = __half22float2(*(const __half2*)(src + kt * 16 + 8));
                }
                uint32_t b0h, b0l, b1h, b1l;
                split2(p0.x, p0.y, b0h, b0l);
                split2(p1.x, p1.y, b1h, b1l);
#pragma unroll
                for (int mt = 0; mt < 2; mt++) {
                    mma_bf16(acc[mt][nt], aH[mt][kt], b0h, b1h);
                    mma_bf16(acc[mt][nt], aH[mt][kt], b0l, b1l);
                    mma_bf16(acc[mt][nt], aL[mt][kt], b0h, b1h);
                }
            }
        }
    }
    float* om = g_offmask + (size_t)b * 27 * HW;
#pragma unroll
    for (int mt = 0; mt < 2; mt++)
#pragma unroll
        for (int rr = 0; rr < 2; rr++) {
            int o = mt * 16 + gid + rr * 8;
            if (o >= 27) continue;
            float bias = (o < 18) ? __ldg(b_off + o) : __ldg(b_msk + o - 18);
#pragma unroll
            for (int nt = 0; nt < 2; nt++) {
                int pos = wid * 16 + nt * 8 + 2 * tig;
                int gp = (ho0 + (pos >> 6)) * Wn + (pos & 63);
                float v0 = acc[mt][nt][rr * 2 + 0] + bias;
                float v1 = acc[mt][nt][rr * 2 + 1] + bias;
                if (o >= 18) {
                    v0 = 1.f / (1.f + __expf(-v0));
                    v1 = 1.f / (1.f + __expf(-v1));
                }
                *(float2*)(om + (size_t)o * HW + gp) = make_float2(v0, v1);
            }
        }
}

// ---------------- k_main pieces ----------------
__device__ __forceinline__ void compute_taps(const float* __restrict__ om, char* tapw,
                                             int lane, int w, int ho0, int j) {
    if (lane >= 16) return;
    int pos = (lane >> 1) * 16 + w * 2 + (lane & 1);
    int row = ho0 + (pos >> 6), col = pos & 63;
    int gp = row * Wn + col;
    int jy = j / 3, jx = j - jy * 3;
    float dy = __ldg(om + (size_t)(2 * j) * HW + gp);
    float dx = __ldg(om + (size_t)(2 * j + 1) * HW + gp);
    float m  = __ldg(om + (size_t)(18 + j) * HW + gp);
    float py = dy + (float)(jy + row - 1);
    float px = dx + (float)(jx + col - 1);
    float y0f = floorf(py), x0f = floorf(px);
    float ly = py - y0f, lx = px - x0f;
    int y0 = (int)y0f, x0 = (int)x0f;
    int4 ti; float4 tw;
    {
        int yy = y0, xx = x0;
        bool v = (yy >= 0) && (yy < Hn) && (xx >= 0) && (xx < Wn);
        ti.x = min(max(yy, 0), Hn - 1) * Wn + min(max(xx, 0), Wn - 1);
        tw.x = v ? (1.f - ly) * (1.f - lx) * m : 0.f;
    }
    {
        int yy = y0, xx = x0 + 1;
        bool v = (yy >= 0) && (yy < Hn) && (xx >= 0) && (xx < Wn);
        ti.y = min(max(yy, 0), Hn - 1) * Wn + min(max(xx, 0), Wn - 1);
        tw.y = v ? (1.f - ly) * lx * m : 0.f;
    }
    {
        int yy = y0 + 1, xx = x0;
        bool v = (yy >= 0) && (yy < Hn) && (xx >= 0) && (xx < Wn);
        ti.z = min(max(yy, 0), Hn - 1) * Wn + min(max(xx, 0), Wn - 1);
        tw.z = v ? ly * (1.f - lx) * m : 0.f;
    }
    {
        int yy = y0 + 1, xx = x0 + 1;
        bool v = (yy >= 0) && (yy < Hn) && (xx >= 0) && (xx < Wn);
        ti.w = min(max(yy, 0), Hn - 1) * Wn + min(max(xx, 0), Wn - 1);
        tw.w = v ? ly * lx * m : 0.f;
    }
    *(int4*)(tapw + lane * 32) = ti;
    *(float4*)(tapw + lane * 32 + 16) = tw;
}

__device__ __forceinline__ void fill_loads(const __half* __restrict__ xtb, const char* tapw,
                                           int lane, int chh, uint2 u[8][4]) {
    const int g = lane & 15, hsel = lane >> 4;
    const __half* base = xtb + chh + g * 4;
#pragma unroll
    for (int k = 0; k < 8; k++) {
        int4 ti = *(const int4*)(tapw + (k * 2 + hsel) * 32);
        u[k][0] = *(const uint2*)(base + (size_t)ti.x * Cn);
        u[k][1] = *(const uint2*)(base + (size_t)ti.y * Cn);
        u[k][2] = *(const uint2*)(base + (size_t)ti.z * Cn);
        u[k][3] = *(const uint2*)(base + (size_t)ti.w * Cn);
    }
}

__device__ __forceinline__ void fill_store(const char* tapw, char* buf,
                                           int w, int lane, uint2 u[8][4]) {
    const int g = lane & 15, hsel = lane >> 4;
#pragma unroll
    for (int k = 0; k < 8; k++) {
        float4 tw = *(const float4*)(tapw + (k * 2 + hsel) * 32 + 16);
        float v0 = 0.f, v1 = 0.f, v2 = 0.f, v3 = 0.f;
#pragma unroll
        for (int tp = 0; tp < 4; tp++) {
            uint2 uu = u[k][tp];
            float2 fa = __half22float2(*reinterpret_cast<__half2*>(&uu.x));
            float2 fb = __half22float2(*reinterpret_cast<__half2*>(&uu.y));
            float wt = (tp == 0) ? tw.x : (tp == 1) ? tw.y : (tp == 2) ? tw.z : tw.w;
            v0 = fmaf(wt, fa.x, v0); v1 = fmaf(wt, fa.y, v1);
            v2 = fmaf(wt, fb.x, v2); v3 = fmaf(wt, fb.y, v3);
        }
        uint32_t hp0, lp0, hp1, lp1;
        split2(v0, v1, hp0, lp0);
        split2(v2, v3, hp1, lp1);
        int pos = k * 16 + w * 2 + hsel;
        *(uint4*)(buf + pos * 288 + g * 16) = make_uint4(hp0, lp0, hp1, lp1);
    }
}

// ---------------- kernel: deformable gather + HMMA GEMM ----------------
// 8 warps, warp tile M=16 x N=128. CTA: 128 pos (2 rows) x 128 out-ch, K=1152.
__global__ __launch_bounds__(256) void k_main_mma(float* __restrict__ out)
{
    extern __shared__ __align__(16) char smem[];
    const int t = threadIdx.x, w = t >> 5, lane = t & 31;
    const int gid = lane >> 2, tig = lane & 3;
    const int b = blockIdx.x >> 5, rp = blockIdx.x & 31, ho0 = rp * 2;
    const __half* xtb = g_xt + (size_t)b * HW * Cn;
    const float* om = g_offmask + (size_t)b * 27 * HW;
    char* tapw = smem + SM_TAPS + w * 512;

    float acc[16][4];
#pragma unroll
    for (int nt = 0; nt < 16; nt++)
#pragma unroll
        for (int r = 0; r < 4; r++) acc[nt][r] = 0.f;

    // prologue: fill buffer 0 (it=0, j=0, ch=0)
    compute_taps(om, tapw, lane, w, ho0, 0);
    __syncwarp();
    {
        uint2 u[8][4];
        fill_loads(xtb, tapw, lane, 0, u);
        fill_store(tapw, smem, w, lane, u);
    }
    __syncthreads();

    for (int it = 0; it < NCH; it++) {
        const int s = it & 1;
        // A fragments for this chunk
        uint32_t aH[4][4], aL[4][4];
        {
            const unsigned char* gb = g_Amain + (size_t)it * 32768 + (size_t)w * 4096 + lane * 16;
#pragma unroll
            for (int kt = 0; kt < 4; kt++) {
                *(uint4*)aH[kt] = *(const uint4*)(gb + kt * 1024);
                *(uint4*)aL[kt] = *(const uint4*)(gb + kt * 1024 + 512);
            }
        }
        // prefetch gather loads for next chunk
        uint2 u[8][4];
        const bool hasNext = (it < NCH - 1);
        if (hasNext) {
            int itn = it + 1;
            if (!(itn & 1)) { compute_taps(om, tapw, lane, w, ho0, itn >> 1); __syncwarp(); }
            fill_loads(xtb, tapw, lane, (itn & 1) * 64, u);
        }
        // mma over current buffer
        const char* bufs = smem + SMB(s);
#pragma unroll
        for (int nt = 0; nt < 16; nt++) {
            const uint2* bp = (const uint2*)(bufs + (nt * 8 + gid) * 288 + tig * 8);
#pragma unroll
            for (int kt = 0; kt < 4; kt++) {
                uint2 b0 = bp[kt * 8];
                uint2 b1 = bp[kt * 8 + 4];
                mma_bf16(acc[nt], aH[kt], b0.x, b1.x);
                mma_bf16(acc[nt], aH[kt], b0.y, b1.y);
                mma_bf16(acc[nt], aL[kt], b0.x, b1.x);
            }
        }
        if (hasNext) fill_store(tapw, smem + SMB(s ^ 1), w, lane, u);
        __syncthreads();
    }

    // epilogue: stage [128 o][132 pad] then coalesced float4 stores
    float* stage = (float*)smem;
    const int r0 = w * 16 + gid;
#pragma unroll
    for (int nt = 0; nt < 16; nt++) {
        int pos0 = nt * 8 + 2 * tig;
        *(float2*)(stage + r0 * 132 + pos0)       = make_float2(acc[nt][0], acc[nt][1]);
        *(float2*)(stage + (r0 + 8) * 132 + pos0) = make_float2(acc[nt][2], acc[nt][3]);
    }
    __syncthreads();
    float* ob = out + (size_t)b * On * HW + (size_t)ho0 * Wn;
#pragma unroll
    for (int e = t; e < 4096; e += 256) {
        int o = e >> 5, p4 = e & 31;
        float4 v = *(float4*)(stage + o * 132 + p4 * 4);
        *(float4*)(ob + (size_t)o * HW + p4 * 4) = v;
    }
}

// ---------------- launch ----------------
extern "C" void kernel_launch(void* const* d_in, const int* in_sizes, int n_in,
                              void* d_out, int out_size) {
    const float* x      = (const float*)d_in[0];
    const float* w_off  = (const float*)d_in[1];
    const float* b_off  = (const float*)d_in[2];
    const float* w_msk  = (const float*)d_in[3];
    const float* b_msk  = (const float*)d_in[4];
    const float* weight = (const float*)d_in[5];
    float* out = (float*)d_out;

    dim3 gxt(HW / 32, Cn / 32, Bn);
    k_xt<<<gxt, dim3(32, 8)>>>(x);
    k_prep<<<(18432 + 4608 + 255) / 256, 256>>>(weight, w_off, w_msk);
    k_offmask_mma<<<Bn * 32, 256>>>(b_off, b_msk);

    static int configured = 0;
    if (!configured) {
        cudaFuncSetAttribute(k_main_mma, cudaFuncAttributeMaxDynamicSharedMemorySize, SM_TOTAL);
        configured = 1;
    }
    k_main_mma<<<Bn * 32, 256, SM_TOTAL>>>(out);
}

// round 5
// speedup vs baseline: 3.5565x; 1.2127x over previous
#include <cuda_runtime.h>
#include <cuda_fp16.h>
#include <cstdint>
#include <math.h>

#define Bn 8
#define Cn 128
#define Hn 64
#define Wn 64
#define On 128
#define K2 9
#define HW 4096
#define CK 1152
#define NCH 18

// ---------------- scratch ----------------
__device__ float g_offmask[Bn * 27 * HW];
__device__ __half g_xt[Bn * HW * Cn];                  // NHWC fp16, channel-permuted per 64-block
// main A frags fp16 hi/lo: [it18][mw4][kt4][mt2][term2][lane32][16B] = 32KB/it
__device__ __align__(16) unsigned char g_Amain[NCH * 32768];
// off A frags: [it18][mt2][kt4][term2][lane32][16B] = 8KB/it
__device__ __align__(16) unsigned char g_Aoff[NCH * 8192];

// k_main smem (bytes): B bufs 2 x (128 pos x 160B) = 40960; taps 2 x 4096; epilogue reuse
#define BPITCH 160
#define SM_TAPS(tb) (40960 + (tb) * 4096)
#define SM_TOTAL 67584

// ---------------- helpers ----------------
__device__ __forceinline__ void split2h(float v0, float v1, uint32_t& hp, uint32_t& lp) {
    __half h0 = __float2half_rn(v0), h1 = __float2half_rn(v1);
    __half l0 = __float2half_rn(v0 - __half2float(h0));
    __half l1 = __float2half_rn(v1 - __half2float(h1));
    __half2 H = __halves2half2(h0, h1);
    __half2 L = __halves2half2(l0, l1);
    hp = *(uint32_t*)&H; lp = *(uint32_t*)&L;
}
__device__ __forceinline__ void mma_f16(float* d, const uint32_t* a, uint32_t b0, uint32_t b1) {
    asm volatile(
        "mma.sync.aligned.m16n8k16.row.col.f32.f16.f16.f32 "
        "{%0,%1,%2,%3},{%4,%5,%6,%7},{%8,%9},{%0,%1,%2,%3};"
        : "+f"(d[0]), "+f"(d[1]), "+f"(d[2]), "+f"(d[3])
        : "r"(a[0]), "r"(a[1]), "r"(a[2]), "r"(a[3]), "r"(b0), "r"(b1));
}
// channel permutation within each 64-block (lc even)
__device__ __forceinline__ int permq(int lc) {
    int kt = lc >> 4, k = lc & 15;
    if (k < 8) return (kt * 4 + (k >> 1)) * 4;
    return (kt * 4 + ((k - 8) >> 1)) * 4 + 2;
}

// ---------------- kernel: NCHW fp32 -> permuted NHWC fp16 ----------------
__global__ __launch_bounds__(256) void k_xt(const float* __restrict__ x) {
    __shared__ float sm[32][33];
    const int tx = threadIdx.x, ty = threadIdx.y;
    const int hw0 = blockIdx.x * 32, c0 = blockIdx.y * 32, b = blockIdx.z;
    const float* xb = x + (size_t)b * Cn * HW;
    __half* xtb = g_xt + (size_t)b * HW * Cn;
#pragma unroll
    for (int i = 0; i < 4; i++)
        sm[ty + i * 8][tx] = xb[(size_t)(c0 + ty + i * 8) * HW + hw0 + tx];
    __syncthreads();
    const int id = ty * 32 + tx;
#pragma unroll
    for (int r = 0; r < 2; r++) {
        int item = id + r * 256;
        int hwl = item >> 4, cp = item & 15;
        int c = c0 + cp * 2;
        int blk = c >> 6, lc = c & 63;
        __half2 h = __floats2half2_rn(sm[cp * 2][hwl], sm[cp * 2 + 1][hwl]);
        *(__half2*)(xtb + (size_t)(hw0 + hwl) * Cn + blk * 64 + permq(lc)) = h;
    }
}

// ---------------- kernel: weight prep (fp16 hi/lo fragments) ----------------
__global__ void k_prep(const float* __restrict__ wmain,
                       const float* __restrict__ woff,
                       const float* __restrict__ wmsk) {
    int i = blockIdx.x * 256 + threadIdx.x;
    if (i < 18432) {
        int lane = i & 31, mt = (i >> 5) & 1, kt = (i >> 6) & 3, mw = (i >> 8) & 3, it = i >> 10;
        int gid = lane >> 2, tig = lane & 3;
        int j = it >> 1, ch = it & 1;
        int r0 = mw * 32 + mt * 16 + gid;
        int cb = ch * 64 + kt * 16 + tig * 2;
        float wv[2][4];
#pragma unroll
        for (int rr = 0; rr < 2; rr++) {
            int r = r0 + rr * 8;
#pragma unroll
            for (int cc = 0; cc < 4; cc++) {
                int c = cb + (cc >> 1) * 8 + (cc & 1);
                wv[rr][cc] = wmain[(size_t)r * CK + c * K2 + j];
            }
        }
        uint4 hi, lo; uint32_t hp, lp;
        split2h(wv[0][0], wv[0][1], hp, lp); hi.x = hp; lo.x = lp;
        split2h(wv[1][0], wv[1][1], hp, lp); hi.y = hp; lo.y = lp;
        split2h(wv[0][2], wv[0][3], hp, lp); hi.z = hp; lo.z = lp;
        split2h(wv[1][2], wv[1][3], hp, lp); hi.w = hp; lo.w = lp;
        size_t base = (size_t)it * 32768 + (size_t)((mw * 4 + kt) * 2 + mt) * 1024 + lane * 16;
        *(uint4*)(g_Amain + base) = hi;
        *(uint4*)(g_Amain + base + 512) = lo;
    } else if (i < 18432 + 4608) {
        int q = i - 18432;
        int lane = q & 31, kt = (q >> 5) & 3, mt = (q >> 7) & 1, it = q >> 8;
        int gid = lane >> 2, tig = lane & 3;
        int j = it >> 1, ch = it & 1;
        int r0 = mt * 16 + gid;
        int cb = ch * 64 + kt * 16 + tig * 2;
        float wv[2][4];
#pragma unroll
        for (int rr = 0; rr < 2; rr++) {
            int r = r0 + rr * 8;
#pragma unroll
            for (int cc = 0; cc < 4; cc++) {
                int c = cb + (cc >> 1) * 8 + (cc & 1);
                float v = 0.f;
                if (r < 18)      v = woff[(size_t)r * CK + c * K2 + j];
                else if (r < 27) v = wmsk[(size_t)(r - 18) * CK + c * K2 + j];
                wv[rr][cc] = v;
            }
        }
        uint4 hi, lo; uint32_t hp, lp;
        split2h(wv[0][0], wv[0][1], hp, lp); hi.x = hp; lo.x = lp;
        split2h(wv[1][0], wv[1][1], hp, lp); hi.y = hp; lo.y = lp;
        split2h(wv[0][2], wv[0][3], hp, lp); hi.z = hp; lo.z = lp;
        split2h(wv[1][2], wv[1][3], hp, lp); hi.w = hp; lo.w = lp;
        size_t base = (size_t)it * 8192 + (size_t)(mt * 4 + kt) * 1024 + lane * 16;
        *(uint4*)(g_Aoff + base) = hi;
        *(uint4*)(g_Aoff + base + 512) = lo;
    }
}

// ---------------- kernel: offset+mask conv (fp16 2-term HMMA) ----------------
__global__ __launch_bounds__(256) void k_offmask_mma(
    const float* __restrict__ b_off, const float* __restrict__ b_msk)
{
    const int t = threadIdx.x, wid = t >> 5, lane = t & 31;
    const int gid = lane >> 2, tig = lane & 3;
    const int b = blockIdx.x >> 5, rp = blockIdx.x & 31, ho0 = rp * 2;
    const __half* xtb = g_xt + (size_t)b * HW * Cn;

    float acc[2][2][4];
#pragma unroll
    for (int mt = 0; mt < 2; mt++)
#pragma unroll
        for (int nt = 0; nt < 2; nt++)
#pragma unroll
            for (int r = 0; r < 4; r++) acc[mt][nt][r] = 0.f;

    for (int it = 0; it < NCH; it++) {
        const int j = it >> 1, ch = it & 1;
        const int jy = j / 3, jx = j - jy * 3;
        uint4 aH[2][4], aL[2][4];
        {
            const unsigned char* gb = g_Aoff + (size_t)it * 8192 + lane * 16;
#pragma unroll
            for (int mt = 0; mt < 2; mt++)
#pragma unroll
                for (int kt = 0; kt < 4; kt++) {
                    size_t o = (size_t)(mt * 4 + kt) * 1024;
                    aH[mt][kt] = __ldg((const uint4*)(gb + o));
                    aL[mt][kt] = __ldg((const uint4*)(gb + o + 512));
                }
        }
#pragma unroll
        for (int nt = 0; nt < 2; nt++) {
            int pos = wid * 16 + nt * 8 + gid;
            int row = ho0 + (pos >> 6), col = pos & 63;
            int sy = row + jy - 1, sx = col + jx - 1;
            bool valid = ((unsigned)sy < Hn) && ((unsigned)sx < Wn);
            const char* src = (const char*)(xtb + (size_t)(valid ? sy * Wn + sx : 0) * Cn + ch * 64);
#pragma unroll
            for (int kt = 0; kt < 4; kt++) {
                uint2 bv = make_uint2(0u, 0u);
                if (valid) bv = *(const uint2*)(src + (kt * 4 + tig) * 8);
#pragma unroll
                for (int mt = 0; mt < 2; mt++) {
                    mma_f16(acc[mt][nt], (const uint32_t*)&aH[mt][kt], bv.x, bv.y);
                    mma_f16(acc[mt][nt], (const uint32_t*)&aL[mt][kt], bv.x, bv.y);
                }
            }
        }
    }
    float* om = g_offmask + (size_t)b * 27 * HW;
#pragma unroll
    for (int mt = 0; mt < 2; mt++)
#pragma unroll
        for (int rr = 0; rr < 2; rr++) {
            int o = mt * 16 + gid + rr * 8;
            if (o >= 27) continue;
            float bias = (o < 18) ? __ldg(b_off + o) : __ldg(b_msk + o - 18);
#pragma unroll
            for (int nt = 0; nt < 2; nt++) {
                int pos = wid * 16 + nt * 8 + 2 * tig;
                int gp = (ho0 + (pos >> 6)) * Wn + (pos & 63);
                float v0 = acc[mt][nt][rr * 2 + 0] + bias;
                float v1 = acc[mt][nt][rr * 2 + 1] + bias;
                if (o >= 18) {
                    v0 = 1.f / (1.f + __expf(-v0));
                    v1 = 1.f / (1.f + __expf(-v1));
                }
                *(float2*)(om + (size_t)o * HW + gp) = make_float2(v0, v1);
            }
        }
}

// ---------------- k_main: tap compute (CTA-wide, 128 pos) ----------------
__device__ __forceinline__ void tap_compute(const float* __restrict__ om, float* tb,
                                            int t, int ho0, int j) {
    if (t >= 128) return;
    int pos = t;
    int row = ho0 + (pos >> 6), col = pos & 63;
    int gp = row * Wn + col;
    int jy = j / 3, jx = j - jy * 3;
    float dy = __ldg(om + (size_t)(2 * j) * HW + gp);
    float dx = __ldg(om + (size_t)(2 * j + 1) * HW + gp);
    float m  = __ldg(om + (size_t)(18 + j) * HW + gp);
    float py = dy + (float)(jy + row - 1);
    float px = dx + (float)(jx + col - 1);
    float y0f = floorf(py), x0f = floorf(px);
    float ly = py - y0f, lx = px - x0f;
    int y0 = (int)y0f, x0 = (int)x0f;
    int4 ti; float4 tw;
    {
        int yy = y0, xx = x0;
        bool v = (yy >= 0) && (yy < Hn) && (xx >= 0) && (xx < Wn);
        ti.x = min(max(yy, 0), Hn - 1) * Wn + min(max(xx, 0), Wn - 1);
        tw.x = v ? (1.f - ly) * (1.f - lx) * m : 0.f;
    }
    {
        int yy = y0, xx = x0 + 1;
        bool v = (yy >= 0) && (yy < Hn) && (xx >= 0) && (xx < Wn);
        ti.y = min(max(yy, 0), Hn - 1) * Wn + min(max(xx, 0), Wn - 1);
        tw.y = v ? (1.f - ly) * lx * m : 0.f;
    }
    {
        int yy = y0 + 1, xx = x0;
        bool v = (yy >= 0) && (yy < Hn) && (xx >= 0) && (xx < Wn);
        ti.z = min(max(yy, 0), Hn - 1) * Wn + min(max(xx, 0), Wn - 1);
        tw.z = v ? ly * (1.f - lx) * m : 0.f;
    }
    {
        int yy = y0 + 1, xx = x0 + 1;
        bool v = (yy >= 0) && (yy < Hn) && (xx >= 0) && (xx < Wn);
        ti.w = min(max(yy, 0), Hn - 1) * Wn + min(max(xx, 0), Wn - 1);
        tw.w = v ? ly * lx * m : 0.f;
    }
    *(int4*)(tb + pos * 8) = ti;
    *(float4*)(tb + pos * 8 + 4) = tw;
}

// ---------------- kernel: deformable gather + fp16 2-term HMMA ----------------
// 512 threads = 16 warps (mw 0..3 x nw 0..3). Warp tile M=32 x N=32.
__global__ __launch_bounds__(512) void k_main_mma(float* __restrict__ out)
{
    extern __shared__ __align__(16) char smem[];
    const int t = threadIdx.x, w = t >> 5, lane = t & 31;
    const int gid = lane >> 2, tig = lane & 3;
    const int mw = w & 3, nw = w >> 2;
    const int gpos = t >> 2, gu = t & 3;
    const int b = blockIdx.x >> 5, rp = blockIdx.x & 31, ho0 = rp * 2;
    const __half* xtb = g_xt + (size_t)b * HW * Cn;
    const float* om = g_offmask + (size_t)b * 27 * HW;

    float acc[2][4][4];
#pragma unroll
    for (int mt = 0; mt < 2; mt++)
#pragma unroll
        for (int nt = 0; nt < 4; nt++)
#pragma unroll
            for (int r = 0; r < 4; r++) acc[mt][nt][r] = 0.f;

    // prologue: taps j0, fill buffer 0
    tap_compute(om, (float*)(smem + SM_TAPS(0)), t, ho0, 0);
    __syncthreads();
    {
        const float* tp = (const float*)(smem + SM_TAPS(0)) + gpos * 8;
        int4 ti = *(const int4*)tp;
        float4 twr = *(const float4*)(tp + 4);
        const __half* xg = xtb + gu * 8;
        uint4 u[8];
        u[0] = __ldg((const uint4*)(xg + (size_t)ti.x * Cn));
        u[1] = __ldg((const uint4*)(xg + (size_t)ti.x * Cn + 32));
        u[2] = __ldg((const uint4*)(xg + (size_t)ti.y * Cn));
        u[3] = __ldg((const uint4*)(xg + (size_t)ti.y * Cn + 32));
        u[4] = __ldg((const uint4*)(xg + (size_t)ti.z * Cn));
        u[5] = __ldg((const uint4*)(xg + (size_t)ti.z * Cn + 32));
        u[6] = __ldg((const uint4*)(xg + (size_t)ti.w * Cn));
        u[7] = __ldg((const uint4*)(xg + (size_t)ti.w * Cn + 32));
        char* bd = smem + gpos * BPITCH;
#pragma unroll
        for (int item = 0; item < 2; item++) {
            float r[8] = {0, 0, 0, 0, 0, 0, 0, 0};
#pragma unroll
            for (int tp4 = 0; tp4 < 4; tp4++) {
                uint4 q = u[tp4 * 2 + item];
                float wt = (tp4 == 0) ? twr.x : (tp4 == 1) ? twr.y : (tp4 == 2) ? twr.z : twr.w;
                const __half2* hh = (const __half2*)&q;
#pragma unroll
                for (int e = 0; e < 4; e++) {
                    float2 f = __half22float2(hh[e]);
                    r[e * 2] = fmaf(wt, f.x, r[e * 2]);
                    r[e * 2 + 1] = fmaf(wt, f.y, r[e * 2 + 1]);
                }
            }
            __half2 o0 = __floats2half2_rn(r[0], r[1]), o1 = __floats2half2_rn(r[2], r[3]);
            __half2 o2 = __floats2half2_rn(r[4], r[5]), o3 = __floats2half2_rn(r[6], r[7]);
            uint4 ov = make_uint4(*(uint32_t*)&o0, *(uint32_t*)&o1, *(uint32_t*)&o2, *(uint32_t*)&o3);
            *(uint4*)(bd + (gu + item * 4) * 16) = ov;
        }
    }
    __syncthreads();

    for (int it = 0; it < NCH; it++) {
        const int s = it & 1;
        const bool hasNext = (it < NCH - 1);
        uint4 u[8];
        float4 twr = make_float4(0, 0, 0, 0);
        if (hasNext) {
            const int itn = it + 1, blk = itn & 1;
            const float* tp = (const float*)(smem + SM_TAPS((itn >> 1) & 1)) + gpos * 8;
            int4 ti = *(const int4*)tp;
            twr = *(const float4*)(tp + 4);
            const __half* xg = xtb + blk * 64 + gu * 8;
            u[0] = __ldg((const uint4*)(xg + (size_t)ti.x * Cn));
            u[1] = __ldg((const uint4*)(xg + (size_t)ti.x * Cn + 32));
            u[2] = __ldg((const uint4*)(xg + (size_t)ti.y * Cn));
            u[3] = __ldg((const uint4*)(xg + (size_t)ti.y * Cn + 32));
            u[4] = __ldg((const uint4*)(xg + (size_t)ti.z * Cn));
            u[5] = __ldg((const uint4*)(xg + (size_t)ti.z * Cn + 32));
            u[6] = __ldg((const uint4*)(xg + (size_t)ti.w * Cn));
            u[7] = __ldg((const uint4*)(xg + (size_t)ti.w * Cn + 32));
        }
        // mma over current buffer
        const char* bs = smem + s * 20480;
        const unsigned char* gA = g_Amain + (size_t)it * 32768 + (size_t)mw * 8192 + lane * 16;
#pragma unroll
        for (int kt = 0; kt < 4; kt++) {
            uint4 aH0 = __ldg((const uint4*)(gA + kt * 2048));
            uint4 aL0 = __ldg((const uint4*)(gA + kt * 2048 + 512));
            uint4 aH1 = __ldg((const uint4*)(gA + kt * 2048 + 1024));
            uint4 aL1 = __ldg((const uint4*)(gA + kt * 2048 + 1536));
#pragma unroll
            for (int nt = 0; nt < 4; nt++) {
                uint2 bv = *(const uint2*)(bs + (nw * 32 + nt * 8 + gid) * BPITCH + (kt * 4 + tig) * 8);
                mma_f16(acc[0][nt], (const uint32_t*)&aH0, bv.x, bv.y);
                mma_f16(acc[0][nt], (const uint32_t*)&aL0, bv.x, bv.y);
                mma_f16(acc[1][nt], (const uint32_t*)&aH1, bv.x, bv.y);
                mma_f16(acc[1][nt], (const uint32_t*)&aL1, bv.x, bv.y);
            }
        }
        if (hasNext) {
            char* bd = smem + (s ^ 1) * 20480 + gpos * BPITCH;
#pragma unroll
            for (int item = 0; item < 2; item++) {
                float r[8] = {0, 0, 0, 0, 0, 0, 0, 0};
#pragma unroll
                for (int tp4 = 0; tp4 < 4; tp4++) {
                    uint4 q = u[tp4 * 2 + item];
                    float wt = (tp4 == 0) ? twr.x : (tp4 == 1) ? twr.y : (tp4 == 2) ? twr.z : twr.w;
                    const __half2* hh = (const __half2*)&q;
#pragma unroll
                    for (int e = 0; e < 4; e++) {
                        float2 f = __half22float2(hh[e]);
                        r[e * 2] = fmaf(wt, f.x, r[e * 2]);
                        r[e * 2 + 1] = fmaf(wt, f.y, r[e * 2 + 1]);
                    }
                }
                __half2 o0 = __floats2half2_rn(r[0], r[1]), o1 = __floats2half2_rn(r[2], r[3]);
                __half2 o2 = __floats2half2_rn(r[4], r[5]), o3 = __floats2half2_rn(r[6], r[7]);
                uint4 ov = make_uint4(*(uint32_t*)&o0, *(uint32_t*)&o1, *(uint32_t*)&o2, *(uint32_t*)&o3);
                *(uint4*)(bd + (gu + item * 4) * 16) = ov;
            }
        }
        // compute taps one j ahead (during even iterations)
        if (((it & 1) == 0) && it < 16)
            tap_compute(om, (float*)(smem + SM_TAPS((it / 2 + 1) & 1)), t, ho0, it / 2 + 1);
        __syncthreads();
    }

    // epilogue
    float* stage = (float*)smem;
#pragma unroll
    for (int mt = 0; mt < 2; mt++) {
        int r0 = mw * 32 + mt * 16 + gid;
#pragma unroll
        for (int nt = 0; nt < 4; nt++) {
            int p0 = nw * 32 + nt * 8 + 2 * tig;
            *(float2*)(stage + r0 * 132 + p0)       = make_float2(acc[mt][nt][0], acc[mt][nt][1]);
            *(float2*)(stage + (r0 + 8) * 132 + p0) = make_float2(acc[mt][nt][2], acc[mt][nt][3]);
        }
    }
    __syncthreads();
    float* ob = out + (size_t)b * On * HW + (size_t)ho0 * Wn;
#pragma unroll
    for (int e = t; e < 4096; e += 512) {
        int o = e >> 5, p4 = e & 31;
        float4 v = *(float4*)(stage + o * 132 + p4 * 4);
        *(float4*)(ob + (size_t)o * HW + p4 * 4) = v;
    }
}

// ---------------- launch ----------------
extern "C" void kernel_launch(void* const* d_in, const int* in_sizes, int n_in,
                              void* d_out, int out_size) {
    const float* x      = (const float*)d_in[0];
    const float* w_off  = (const float*)d_in[1];
    const float* b_off  = (const float*)d_in[2];
    const float* w_msk  = (const float*)d_in[3];
    const float* b_msk  = (const float*)d_in[4];
    const float* weight = (const float*)d_in[5];
    float* out = (float*)d_out;

    dim3 gxt(HW / 32, Cn / 32, Bn);
    k_xt<<<gxt, dim3(32, 8)>>>(x);
    k_prep<<<(18432 + 4608 + 255) / 256, 256>>>(weight, w_off, w_msk);
    k_offmask_mma<<<Bn * 32, 256>>>(b_off, b_msk);

    static int configured = 0;
    if (!configured) {
        cudaFuncSetAttribute(k_main_mma, cudaFuncAttributeMaxDynamicSharedMemorySize, SM_TOTAL);
        configured = 1;
    }
    k_main_mma<<<Bn * 32, 512, SM_TOTAL>>>(out);
}

// round 7
// speedup vs baseline: 4.1377x; 1.1634x over previous
#include <cuda_runtime.h>
#include <cuda_fp16.h>
#include <cstdint>
#include <math.h>

#define Bn 8
#define Cn 128
#define Hn 64
#define Wn 64
#define On 128
#define K2 9
#define HW 4096
#define CK 1152
#define NCH 18

// ---------------- scratch ----------------
__device__ float g_offmask[Bn * 27 * HW];
__device__ __half g_xt[Bn * HW * Cn];                  // NHWC fp16, channel-permuted per 64-block
// main A frags fp16 hi/lo: [it18][mw4][kt4][mt2][term2][lane32][16B] = 32KB/it
__device__ __align__(16) unsigned char g_Amain[NCH * 32768];
// off A frags: [it18][mt2][kt4][term2][lane32][16B] = 8KB/it
__device__ __align__(16) unsigned char g_Aoff[NCH * 8192];

// k_main smem (bytes): B bufs 2 x (64 pos x 160B) = 20480; taps 2 x 2048
#define BPITCH 160
#define SMB(s)    ((s) * 10240)
#define SM_TAPS(tb) (20480 + (tb) * 2048)
#define SM_TOTAL 24576

// ---------------- helpers ----------------
__device__ __forceinline__ void split2h(float v0, float v1, uint32_t& hp, uint32_t& lp) {
    __half h0 = __float2half_rn(v0), h1 = __float2half_rn(v1);
    __half l0 = __float2half_rn(v0 - __half2float(h0));
    __half l1 = __float2half_rn(v1 - __half2float(h1));
    __half2 H = __halves2half2(h0, h1);
    __half2 L = __halves2half2(l0, l1);
    hp = *(uint32_t*)&H; lp = *(uint32_t*)&L;
}
__device__ __forceinline__ void mma_f16(float* d, const uint32_t* a, uint32_t b0, uint32_t b1) {
    asm volatile(
        "mma.sync.aligned.m16n8k16.row.col.f32.f16.f16.f32 "
        "{%0,%1,%2,%3},{%4,%5,%6,%7},{%8,%9},{%0,%1,%2,%3};"
        : "+f"(d[0]), "+f"(d[1]), "+f"(d[2]), "+f"(d[3])
        : "r"(a[0]), "r"(a[1]), "r"(a[2]), "r"(a[3]), "r"(b0), "r"(b1));
}
// channel permutation within each 64-block (lc even)
__device__ __forceinline__ int permq(int lc) {
    int kt = lc >> 4, k = lc & 15;
    if (k < 8) return (kt * 4 + (k >> 1)) * 4;
    return (kt * 4 + ((k - 8) >> 1)) * 4 + 2;
}

// ---------------- kernel: NCHW fp32 -> permuted NHWC fp16 ----------------
__global__ __launch_bounds__(256) void k_xt(const float* __restrict__ x) {
    __shared__ float sm[32][33];
    const int tx = threadIdx.x, ty = threadIdx.y;
    const int hw0 = blockIdx.x * 32, c0 = blockIdx.y * 32, b = blockIdx.z;
    const float* xb = x + (size_t)b * Cn * HW;
    __half* xtb = g_xt + (size_t)b * HW * Cn;
#pragma unroll
    for (int i = 0; i < 4; i++)
        sm[ty + i * 8][tx] = xb[(size_t)(c0 + ty + i * 8) * HW + hw0 + tx];
    __syncthreads();
    const int id = ty * 32 + tx;
#pragma unroll
    for (int r = 0; r < 2; r++) {
        int item = id + r * 256;
        int hwl = item >> 4, cp = item & 15;
        int c = c0 + cp * 2;
        int blk = c >> 6, lc = c & 63;
        __half2 h = __floats2half2_rn(sm[cp * 2][hwl], sm[cp * 2 + 1][hwl]);
        *(__half2*)(xtb + (size_t)(hw0 + hwl) * Cn + blk * 64 + permq(lc)) = h;
    }
}

// ---------------- kernel: weight prep (fp16 hi/lo fragments) ----------------
__global__ void k_prep(const float* __restrict__ wmain,
                       const float* __restrict__ woff,
                       const float* __restrict__ wmsk) {
    int i = blockIdx.x * 256 + threadIdx.x;
    if (i < 18432) {
        int lane = i & 31, mt = (i >> 5) & 1, kt = (i >> 6) & 3, mw = (i >> 8) & 3, it = i >> 10;
        int gid = lane >> 2, tig = lane & 3;
        int j = it >> 1, ch = it & 1;
        int r0 = mw * 32 + mt * 16 + gid;
        int cb = ch * 64 + kt * 16 + tig * 2;
        float wv[2][4];
#pragma unroll
        for (int rr = 0; rr < 2; rr++) {
            int r = r0 + rr * 8;
#pragma unroll
            for (int cc = 0; cc < 4; cc++) {
                int c = cb + (cc >> 1) * 8 + (cc & 1);
                wv[rr][cc] = wmain[(size_t)r * CK + c * K2 + j];
            }
        }
        uint4 hi, lo; uint32_t hp, lp;
        split2h(wv[0][0], wv[0][1], hp, lp); hi.x = hp; lo.x = lp;
        split2h(wv[1][0], wv[1][1], hp, lp); hi.y = hp; lo.y = lp;
        split2h(wv[0][2], wv[0][3], hp, lp); hi.z = hp; lo.z = lp;
        split2h(wv[1][2], wv[1][3], hp, lp); hi.w = hp; lo.w = lp;
        size_t base = (size_t)it * 32768 + (size_t)((mw * 4 + kt) * 2 + mt) * 1024 + lane * 16;
        *(uint4*)(g_Amain + base) = hi;
        *(uint4*)(g_Amain + base + 512) = lo;
    } else if (i < 18432 + 4608) {
        int q = i - 18432;
        int lane = q & 31, kt = (q >> 5) & 3, mt = (q >> 7) & 1, it = q >> 8;
        int gid = lane >> 2, tig = lane & 3;
        int j = it >> 1, ch = it & 1;
        int r0 = mt * 16 + gid;
        int cb = ch * 64 + kt * 16 + tig * 2;
        float wv[2][4];
#pragma unroll
        for (int rr = 0; rr < 2; rr++) {
            int r = r0 + rr * 8;
#pragma unroll
            for (int cc = 0; cc < 4; cc++) {
                int c = cb + (cc >> 1) * 8 + (cc & 1);
                float v = 0.f;
                if (r < 18)      v = woff[(size_t)r * CK + c * K2 + j];
                else if (r < 27) v = wmsk[(size_t)(r - 18) * CK + c * K2 + j];
                wv[rr][cc] = v;
            }
        }
        uint4 hi, lo; uint32_t hp, lp;
        split2h(wv[0][0], wv[0][1], hp, lp); hi.x = hp; lo.x = lp;
        split2h(wv[1][0], wv[1][1], hp, lp); hi.y = hp; lo.y = lp;
        split2h(wv[0][2], wv[0][3], hp, lp); hi.z = hp; lo.z = lp;
        split2h(wv[1][2], wv[1][3], hp, lp); hi.w = hp; lo.w = lp;
        size_t base = (size_t)it * 8192 + (size_t)(mt * 4 + kt) * 1024 + lane * 16;
        *(uint4*)(g_Aoff + base) = hi;
        *(uint4*)(g_Aoff + base + 512) = lo;
    }
}

// ---------------- kernel: offset+mask conv (fp16 2-term HMMA) ----------------
__global__ __launch_bounds__(256) void k_offmask_mma(
    const float* __restrict__ b_off, const float* __restrict__ b_msk)
{
    const int t = threadIdx.x, wid = t >> 5, lane = t & 31;
    const int gid = lane >> 2, tig = lane & 3;
    const int b = blockIdx.x >> 5, rp = blockIdx.x & 31, ho0 = rp * 2;
    const __half* xtb = g_xt + (size_t)b * HW * Cn;

    float acc[2][2][4];
#pragma unroll
    for (int mt = 0; mt < 2; mt++)
#pragma unroll
        for (int nt = 0; nt < 2; nt++)
#pragma unroll
            for (int r = 0; r < 4; r++) acc[mt][nt][r] = 0.f;

    for (int it = 0; it < NCH; it++) {
        const int j = it >> 1, ch = it & 1;
        const int jy = j / 3, jx = j - jy * 3;
        uint4 aH[2][4], aL[2][4];
        {
            const unsigned char* gb = g_Aoff + (size_t)it * 8192 + lane * 16;
#pragma unroll
            for (int mt = 0; mt < 2; mt++)
#pragma unroll
                for (int kt = 0; kt < 4; kt++) {
                    size_t o = (size_t)(mt * 4 + kt) * 1024;
                    aH[mt][kt] = __ldg((const uint4*)(gb + o));
                    aL[mt][kt] = __ldg((const uint4*)(gb + o + 512));
                }
        }
#pragma unroll
        for (int nt = 0; nt < 2; nt++) {
            int pos = wid * 16 + nt * 8 + gid;
            int row = ho0 + (pos >> 6), col = pos & 63;
            int sy = row + jy - 1, sx = col + jx - 1;
            bool valid = ((unsigned)sy < Hn) && ((unsigned)sx < Wn);
            const char* src = (const char*)(xtb + (size_t)(valid ? sy * Wn + sx : 0) * Cn + ch * 64);
#pragma unroll
            for (int kt = 0; kt < 4; kt++) {
                uint2 bv = make_uint2(0u, 0u);
                if (valid) bv = *(const uint2*)(src + (kt * 4 + tig) * 8);
#pragma unroll
                for (int mt = 0; mt < 2; mt++) {
                    mma_f16(acc[mt][nt], (const uint32_t*)&aH[mt][kt], bv.x, bv.y);
                    mma_f16(acc[mt][nt], (const uint32_t*)&aL[mt][kt], bv.x, bv.y);
                }
            }
        }
    }
    float* om = g_offmask + (size_t)b * 27 * HW;
#pragma unroll
    for (int mt = 0; mt < 2; mt++)
#pragma unroll
        for (int rr = 0; rr < 2; rr++) {
            int o = mt * 16 + gid + rr * 8;
            if (o >= 27) continue;
            float bias = (o < 18) ? __ldg(b_off + o) : __ldg(b_msk + o - 18);
#pragma unroll
            for (int nt = 0; nt < 2; nt++) {
                int pos = wid * 16 + nt * 8 + 2 * tig;
                int gp = (ho0 + (pos >> 6)) * Wn + (pos & 63);
                float v0 = acc[mt][nt][rr * 2 + 0] + bias;
                float v1 = acc[mt][nt][rr * 2 + 1] + bias;
                if (o >= 18) {
                    v0 = 1.f / (1.f + __expf(-v0));
                    v1 = 1.f / (1.f + __expf(-v1));
                }
                *(float2*)(om + (size_t)o * HW + gp) = make_float2(v0, v1);
            }
        }
}

// ---------------- k_main: tap compute (64 pos, one row) ----------------
__device__ __forceinline__ void tap_compute(const float* __restrict__ om, float* tb,
                                            int t, int ho, int j) {
    if (t >= 64) return;
    int col = t;
    int gp = ho * Wn + col;
    int jy = j / 3, jx = j - jy * 3;
    float dy = __ldg(om + (size_t)(2 * j) * HW + gp);
    float dx = __ldg(om + (size_t)(2 * j + 1) * HW + gp);
    float m  = __ldg(om + (size_t)(18 + j) * HW + gp);
    float py = dy + (float)(jy + ho - 1);
    float px = dx + (float)(jx + col - 1);
    float y0f = floorf(py), x0f = floorf(px);
    float ly = py - y0f, lx = px - x0f;
    int y0 = (int)y0f, x0 = (int)x0f;
    int4 ti; float4 tw;
    {
        int yy = y0, xx = x0;
        bool v = (yy >= 0) && (yy < Hn) && (xx >= 0) && (xx < Wn);
        ti.x = min(max(yy, 0), Hn - 1) * Wn + min(max(xx, 0), Wn - 1);
        tw.x = v ? (1.f - ly) * (1.f - lx) * m : 0.f;
    }
    {
        int yy = y0, xx = x0 + 1;
        bool v = (yy >= 0) && (yy < Hn) && (xx >= 0) && (xx < Wn);
        ti.y = min(max(yy, 0), Hn - 1) * Wn + min(max(xx, 0), Wn - 1);
        tw.y = v ? (1.f - ly) * lx * m : 0.f;
    }
    {
        int yy = y0 + 1, xx = x0;
        bool v = (yy >= 0) && (yy < Hn) && (xx >= 0) && (xx < Wn);
        ti.z = min(max(yy, 0), Hn - 1) * Wn + min(max(xx, 0), Wn - 1);
        tw.z = v ? ly * (1.f - lx) * m : 0.f;
    }
    {
        int yy = y0 + 1, xx = x0 + 1;
        bool v = (yy >= 0) && (yy < Hn) && (xx >= 0) && (xx < Wn);
        ti.w = min(max(yy, 0), Hn - 1) * Wn + min(max(xx, 0), Wn - 1);
        tw.w = v ? ly * lx * m : 0.f;
    }
    *(int4*)(tb + col * 8) = ti;
    *(float4*)(tb + col * 8 + 4) = tw;
}

// gather -> fp16 combine -> store one position's 64 channels for this quarter-thread
__device__ __forceinline__ void b_combine_store(char* bd, const uint4* u, float4 twr, int gu) {
#pragma unroll
    for (int item = 0; item < 2; item++) {
        float r[8] = {0, 0, 0, 0, 0, 0, 0, 0};
#pragma unroll
        for (int tp4 = 0; tp4 < 4; tp4++) {
            uint4 q = u[tp4 * 2 + item];
            float wt = (tp4 == 0) ? twr.x : (tp4 == 1) ? twr.y : (tp4 == 2) ? twr.z : twr.w;
            const __half2* hh = (const __half2*)&q;
#pragma unroll
            for (int e = 0; e < 4; e++) {
                float2 f = __half22float2(hh[e]);
                r[e * 2] = fmaf(wt, f.x, r[e * 2]);
                r[e * 2 + 1] = fmaf(wt, f.y, r[e * 2 + 1]);
            }
        }
        __half2 o0 = __floats2half2_rn(r[0], r[1]), o1 = __floats2half2_rn(r[2], r[3]);
        __half2 o2 = __floats2half2_rn(r[4], r[5]), o3 = __floats2half2_rn(r[6], r[7]);
        uint4 ov = make_uint4(*(uint32_t*)&o0, *(uint32_t*)&o1, *(uint32_t*)&o2, *(uint32_t*)&o3);
        *(uint4*)(bd + (gu + item * 4) * 16) = ov;
    }
}

__device__ __forceinline__ void gather_loads(const __half* xg, int4 ti, uint4* u) {
    u[0] = __ldg((const uint4*)(xg + (size_t)ti.x * Cn));
    u[1] = __ldg((const uint4*)(xg + (size_t)ti.x * Cn + 32));
    u[2] = __ldg((const uint4*)(xg + (size_t)ti.y * Cn));
    u[3] = __ldg((const uint4*)(xg + (size_t)ti.y * Cn + 32));
    u[4] = __ldg((const uint4*)(xg + (size_t)ti.z * Cn));
    u[5] = __ldg((const uint4*)(xg + (size_t)ti.z * Cn + 32));
    u[6] = __ldg((const uint4*)(xg + (size_t)ti.w * Cn));
    u[7] = __ldg((const uint4*)(xg + (size_t)ti.w * Cn + 32));
}

// ---------------- kernel: deformable gather + fp16 2-term HMMA ----------------
// 256 threads = 8 warps (mw 0..3 x nw 0..1). Warp tile M=32 x N=32.
// CTA: 1 output row (64 pos) x 128 out-ch, K=1152. 2 CTAs/SM.
__global__ __launch_bounds__(256, 2) void k_main_mma(float* __restrict__ out)
{
    extern __shared__ __align__(16) char smem[];
    const int t = threadIdx.x, w = t >> 5, lane = t & 31;
    const int gid = lane >> 2, tig = lane & 3;
    const int mw = w & 3, nw = w >> 2;
    const int gpos = t >> 2, gu = t & 3;
    const int b = blockIdx.x >> 6, ho = blockIdx.x & 63;
    const __half* xtb = g_xt + (size_t)b * HW * Cn;
    const float* om = g_offmask + (size_t)b * 27 * HW;

    float acc[2][4][4];
#pragma unroll
    for (int mt = 0; mt < 2; mt++)
#pragma unroll
        for (int nt = 0; nt < 4; nt++)
#pragma unroll
            for (int r = 0; r < 4; r++) acc[mt][nt][r] = 0.f;

    // prologue: taps j0, fill buffer 0
    tap_compute(om, (float*)(smem + SM_TAPS(0)), t, ho, 0);
    __syncthreads();
    {
        const float* tp = (const float*)(smem + SM_TAPS(0)) + gpos * 8;
        int4 ti = *(const int4*)tp;
        float4 twr = *(const float4*)(tp + 4);
        uint4 u[8];
        gather_loads(xtb + gu * 8, ti, u);
        b_combine_store(smem + gpos * BPITCH, u, twr, gu);
    }
    __syncthreads();

    for (int it = 0; it < NCH; it++) {
        const int s = it & 1;
        const bool hasNext = (it < NCH - 1);
        uint4 u[8];
        float4 twr = make_float4(0, 0, 0, 0);
        if (hasNext) {
            const int itn = it + 1, blk = itn & 1;
            const float* tp = (const float*)(smem + SM_TAPS((itn >> 1) & 1)) + gpos * 8;
            int4 ti = *(const int4*)tp;
            twr = *(const float4*)(tp + 4);
            gather_loads(xtb + blk * 64 + gu * 8, ti, u);
        }
        // mma over current buffer
        const char* bs = smem + SMB(s);
        const unsigned char* gA = g_Amain + (size_t)it * 32768 + (size_t)mw * 8192 + lane * 16;
#pragma unroll
        for (int kt = 0; kt < 4; kt++) {
            uint4 aH0 = __ldg((const uint4*)(gA + kt * 2048));
            uint4 aL0 = __ldg((const uint4*)(gA + kt * 2048 + 512));
            uint4 aH1 = __ldg((const uint4*)(gA + kt * 2048 + 1024));
            uint4 aL1 = __ldg((const uint4*)(gA + kt * 2048 + 1536));
#pragma unroll
            for (int nt = 0; nt < 4; nt++) {
                uint2 bv = *(const uint2*)(bs + (nw * 32 + nt * 8 + gid) * BPITCH + (kt * 4 + tig) * 8);
                mma_f16(acc[0][nt], (const uint32_t*)&aH0, bv.x, bv.y);
                mma_f16(acc[0][nt], (const uint32_t*)&aL0, bv.x, bv.y);
                mma_f16(acc[1][nt], (const uint32_t*)&aH1, bv.x, bv.y);
                mma_f16(acc[1][nt], (const uint32_t*)&aL1, bv.x, bv.y);
            }
        }
        if (hasNext)
            b_combine_store(smem + SMB(s ^ 1) + gpos * BPITCH, u, twr, gu);
        // compute taps one j ahead (during even iterations)
        if (((it & 1) == 0) && it < 16)
            tap_compute(om, (float*)(smem + SM_TAPS((it / 2 + 1) & 1)), t, ho, it / 2 + 1);
        __syncthreads();
    }

    // epilogue: two halves of 64 output channels, staged via smem (pitch 68 floats = 272B, 16B-aligned)
    float* ob = out + (size_t)b * On * HW + (size_t)ho * Wn;
    float* stage = (float*)smem;   // 64 rows x 68 floats = 17.4KB
#pragma unroll
    for (int half = 0; half < 2; half++) {
        if ((mw >> 1) == half) {
            int rbase = (mw & 1) * 32 + gid;
#pragma unroll
            for (int mt = 0; mt < 2; mt++)
#pragma unroll
                for (int nt = 0; nt < 4; nt++) {
                    int p0 = nw * 32 + nt * 8 + 2 * tig;
                    *(float2*)(stage + (rbase + mt * 16) * 68 + p0) =
                        make_float2(acc[mt][nt][0], acc[mt][nt][1]);
                    *(float2*)(stage + (rbase + mt * 16 + 8) * 68 + p0) =
                        make_float2(acc[mt][nt][2], acc[mt][nt][3]);
                }
        }
        __syncthreads();
#pragma unroll
        for (int e = t; e < 1024; e += 256) {
            int o = e >> 4, q = e & 15;
            float4 v = *(float4*)(stage + o * 68 + q * 4);
            *(float4*)(ob + (size_t)(half * 64 + o) * HW + q * 4) = v;
        }
        __syncthreads();
    }
}

// ---------------- launch ----------------
extern "C" void kernel_launch(void* const* d_in, const int* in_sizes, int n_in,
                              void* d_out, int out_size) {
    const float* x      = (const float*)d_in[0];
    const float* w_off  = (const float*)d_in[1];
    const float* b_off  = (const float*)d_in[2];
    const float* w_msk  = (const float*)d_in[3];
    const float* b_msk  = (const float*)d_in[4];
    const float* weight = (const float*)d_in[5];
    float* out = (float*)d_out;

    dim3 gxt(HW / 32, Cn / 32, Bn);
    k_xt<<<gxt, dim3(32, 8)>>>(x);
    k_prep<<<(18432 + 4608 + 255) / 256, 256>>>(weight, w_off, w_msk);
    k_offmask_mma<<<Bn * 32, 256>>>(b_off, b_msk);
    k_main_mma<<<Bn * 64, 256, SM_TOTAL>>>(out);
}

// round 8
// speedup vs baseline: 4.4668x; 1.0795x over previous
#include <cuda_runtime.h>
#include <cuda_fp16.h>
#include <cstdint>
#include <math.h>

#define Bn 8
#define Cn 128
#define Hn 64
#define Wn 64
#define On 128
#define K2 9
#define HW 4096
#define CK 1152
#define NCH 18

// ---------------- scratch ----------------
__device__ float g_offmask[Bn * 27 * HW];
__device__ __half g_xt[Bn * HW * Cn];                  // NHWC fp16, channel-permuted per 64-block
// main A frags fp16 hi/lo: [it18][mw4][kt4][mt2][term2][lane32][16B] = 32KB/it
__device__ __align__(16) unsigned char g_Amain[NCH * 32768];
// off A frags: [it18][mt2][kt4][term2][lane32][16B] = 8KB/it
__device__ __align__(16) unsigned char g_Aoff[NCH * 8192];

// k_main smem (bytes): B bufs 2 x (64 pos x 160B) = 20480; taps 2 x 2048
#define BPITCH 160
#define SMB(s)    ((s) * 10240)
#define SM_TAPS(tb) (20480 + (tb) * 2048)
#define SM_TOTAL 24576

// ---------------- helpers ----------------
__device__ __forceinline__ void split2h(float v0, float v1, uint32_t& hp, uint32_t& lp) {
    __half h0 = __float2half_rn(v0), h1 = __float2half_rn(v1);
    __half l0 = __float2half_rn(v0 - __half2float(h0));
    __half l1 = __float2half_rn(v1 - __half2float(h1));
    __half2 H = __halves2half2(h0, h1);
    __half2 L = __halves2half2(l0, l1);
    hp = *(uint32_t*)&H; lp = *(uint32_t*)&L;
}
__device__ __forceinline__ void mma_f16(float* d, const uint32_t* a, uint32_t b0, uint32_t b1) {
    asm volatile(
        "mma.sync.aligned.m16n8k16.row.col.f32.f16.f16.f32 "
        "{%0,%1,%2,%3},{%4,%5,%6,%7},{%8,%9},{%0,%1,%2,%3};"
        : "+f"(d[0]), "+f"(d[1]), "+f"(d[2]), "+f"(d[3])
        : "r"(a[0]), "r"(a[1]), "r"(a[2]), "r"(a[3]), "r"(b0), "r"(b1));
}
// channel permutation within each 64-block (lc even)
__device__ __forceinline__ int permq(int lc) {
    int kt = lc >> 4, k = lc & 15;
    if (k < 8) return (kt * 4 + (k >> 1)) * 4;
    return (kt * 4 + ((k - 8) >> 1)) * 4 + 2;
}

// ---------------- kernel: NCHW fp32 -> permuted NHWC fp16 ----------------
__global__ __launch_bounds__(256) void k_xt(const float* __restrict__ x) {
    __shared__ float sm[32][33];
    const int tx = threadIdx.x, ty = threadIdx.y;
    const int hw0 = blockIdx.x * 32, c0 = blockIdx.y * 32, b = blockIdx.z;
    const float* xb = x + (size_t)b * Cn * HW;
    __half* xtb = g_xt + (size_t)b * HW * Cn;
#pragma unroll
    for (int i = 0; i < 4; i++)
        sm[ty + i * 8][tx] = xb[(size_t)(c0 + ty + i * 8) * HW + hw0 + tx];
    __syncthreads();
    const int id = ty * 32 + tx;
#pragma unroll
    for (int r = 0; r < 2; r++) {
        int item = id + r * 256;
        int hwl = item >> 4, cp = item & 15;
        int c = c0 + cp * 2;
        int blk = c >> 6, lc = c & 63;
        __half2 h = __floats2half2_rn(sm[cp * 2][hwl], sm[cp * 2 + 1][hwl]);
        *(__half2*)(xtb + (size_t)(hw0 + hwl) * Cn + blk * 64 + permq(lc)) = h;
    }
}

// ---------------- kernel: weight prep (fp16 hi/lo fragments) ----------------
__global__ void k_prep(const float* __restrict__ wmain,
                       const float* __restrict__ woff,
                       const float* __restrict__ wmsk) {
    int i = blockIdx.x * 256 + threadIdx.x;
    if (i < 18432) {
        int lane = i & 31, mt = (i >> 5) & 1, kt = (i >> 6) & 3, mw = (i >> 8) & 3, it = i >> 10;
        int gid = lane >> 2, tig = lane & 3;
        int j = it >> 1, ch = it & 1;
        int r0 = mw * 32 + mt * 16 + gid;
        int cb = ch * 64 + kt * 16 + tig * 2;
        float wv[2][4];
#pragma unroll
        for (int rr = 0; rr < 2; rr++) {
            int r = r0 + rr * 8;
#pragma unroll
            for (int cc = 0; cc < 4; cc++) {
                int c = cb + (cc >> 1) * 8 + (cc & 1);
                wv[rr][cc] = wmain[(size_t)r * CK + c * K2 + j];
            }
        }
        uint4 hi, lo; uint32_t hp, lp;
        split2h(wv[0][0], wv[0][1], hp, lp); hi.x = hp; lo.x = lp;
        split2h(wv[1][0], wv[1][1], hp, lp); hi.y = hp; lo.y = lp;
        split2h(wv[0][2], wv[0][3], hp, lp); hi.z = hp; lo.z = lp;
        split2h(wv[1][2], wv[1][3], hp, lp); hi.w = hp; lo.w = lp;
        size_t base = (size_t)it * 32768 + (size_t)((mw * 4 + kt) * 2 + mt) * 1024 + lane * 16;
        *(uint4*)(g_Amain + base) = hi;
        *(uint4*)(g_Amain + base + 512) = lo;
    } else if (i < 18432 + 4608) {
        int q = i - 18432;
        int lane = q & 31, kt = (q >> 5) & 3, mt = (q >> 7) & 1, it = q >> 8;
        int gid = lane >> 2, tig = lane & 3;
        int j = it >> 1, ch = it & 1;
        int r0 = mt * 16 + gid;
        int cb = ch * 64 + kt * 16 + tig * 2;
        float wv[2][4];
#pragma unroll
        for (int rr = 0; rr < 2; rr++) {
            int r = r0 + rr * 8;
#pragma unroll
            for (int cc = 0; cc < 4; cc++) {
                int c = cb + (cc >> 1) * 8 + (cc & 1);
                float v = 0.f;
                if (r < 18)      v = woff[(size_t)r * CK + c * K2 + j];
                else if (r < 27) v = wmsk[(size_t)(r - 18) * CK + c * K2 + j];
                wv[rr][cc] = v;
            }
        }
        uint4 hi, lo; uint32_t hp, lp;
        split2h(wv[0][0], wv[0][1], hp, lp); hi.x = hp; lo.x = lp;
        split2h(wv[1][0], wv[1][1], hp, lp); hi.y = hp; lo.y = lp;
        split2h(wv[0][2], wv[0][3], hp, lp); hi.z = hp; lo.z = lp;
        split2h(wv[1][2], wv[1][3], hp, lp); hi.w = hp; lo.w = lp;
        size_t base = (size_t)it * 8192 + (size_t)(mt * 4 + kt) * 1024 + lane * 16;
        *(uint4*)(g_Aoff + base) = hi;
        *(uint4*)(g_Aoff + base + 512) = lo;
    }
}

// ---------------- kernel: offset+mask conv (fp16 2-term HMMA) ----------------
// 128 threads = 4 warps, warp tile M=32 x N=32. CTA covers 128 pos (2 rows).
__global__ __launch_bounds__(128) void k_offmask_mma(
    const float* __restrict__ b_off, const float* __restrict__ b_msk)
{
    const int t = threadIdx.x, w = t >> 5, lane = t & 31;
    const int gid = lane >> 2, tig = lane & 3;
    const int b = blockIdx.x >> 5, rp = blockIdx.x & 31, ho0 = rp * 2;
    const __half* xtb = g_xt + (size_t)b * HW * Cn;

    float acc[2][4][4];
#pragma unroll
    for (int mt = 0; mt < 2; mt++)
#pragma unroll
        for (int nt = 0; nt < 4; nt++)
#pragma unroll
            for (int r = 0; r < 4; r++) acc[mt][nt][r] = 0.f;

    for (int it = 0; it < NCH; it++) {
        const int j = it >> 1, ch = it & 1;
        const int jy = j / 3, jx = j - jy * 3;
        uint4 aH[2][4], aL[2][4];
        {
            const unsigned char* gb = g_Aoff + (size_t)it * 8192 + lane * 16;
#pragma unroll
            for (int mt = 0; mt < 2; mt++)
#pragma unroll
                for (int kt = 0; kt < 4; kt++) {
                    size_t o = (size_t)(mt * 4 + kt) * 1024;
                    aH[mt][kt] = __ldg((const uint4*)(gb + o));
                    aL[mt][kt] = __ldg((const uint4*)(gb + o + 512));
                }
        }
#pragma unroll
        for (int nt = 0; nt < 4; nt++) {
            int pos = w * 32 + nt * 8 + gid;
            int row = ho0 + (pos >> 6), col = pos & 63;
            int sy = row + jy - 1, sx = col + jx - 1;
            bool valid = ((unsigned)sy < Hn) && ((unsigned)sx < Wn);
            const char* src = (const char*)(xtb + (size_t)(valid ? sy * Wn + sx : 0) * Cn + ch * 64);
#pragma unroll
            for (int kt = 0; kt < 4; kt++) {
                uint2 bv = make_uint2(0u, 0u);
                if (valid) bv = *(const uint2*)(src + (kt * 4 + tig) * 8);
#pragma unroll
                for (int mt = 0; mt < 2; mt++) {
                    mma_f16(acc[mt][nt], (const uint32_t*)&aH[mt][kt], bv.x, bv.y);
                    mma_f16(acc[mt][nt], (const uint32_t*)&aL[mt][kt], bv.x, bv.y);
                }
            }
        }
    }
    float* om = g_offmask + (size_t)b * 27 * HW;
#pragma unroll
    for (int mt = 0; mt < 2; mt++)
#pragma unroll
        for (int rr = 0; rr < 2; rr++) {
            int o = mt * 16 + gid + rr * 8;
            if (o >= 27) continue;
            float bias = (o < 18) ? __ldg(b_off + o) : __ldg(b_msk + o - 18);
#pragma unroll
            for (int nt = 0; nt < 4; nt++) {
                int pos = w * 32 + nt * 8 + 2 * tig;
                int gp = (ho0 + (pos >> 6)) * Wn + (pos & 63);
                float v0 = acc[mt][nt][rr * 2 + 0] + bias;
                float v1 = acc[mt][nt][rr * 2 + 1] + bias;
                if (o >= 18) {
                    v0 = 1.f / (1.f + __expf(-v0));
                    v1 = 1.f / (1.f + __expf(-v1));
                }
                *(float2*)(om + (size_t)o * HW + gp) = make_float2(v0, v1);
            }
        }
}

// ---------------- k_main: tap compute (64 pos, one row) ----------------
__device__ __forceinline__ void tap_compute(const float* __restrict__ om, float* tb,
                                            int t, int ho, int j) {
    if (t >= 64) return;
    int col = t;
    int gp = ho * Wn + col;
    int jy = j / 3, jx = j - jy * 3;
    float dy = __ldg(om + (size_t)(2 * j) * HW + gp);
    float dx = __ldg(om + (size_t)(2 * j + 1) * HW + gp);
    float m  = __ldg(om + (size_t)(18 + j) * HW + gp);
    float py = dy + (float)(jy + ho - 1);
    float px = dx + (float)(jx + col - 1);
    float y0f = floorf(py), x0f = floorf(px);
    float ly = py - y0f, lx = px - x0f;
    int y0 = (int)y0f, x0 = (int)x0f;
    int4 ti; float4 tw;
    {
        int yy = y0, xx = x0;
        bool v = (yy >= 0) && (yy < Hn) && (xx >= 0) && (xx < Wn);
        ti.x = min(max(yy, 0), Hn - 1) * Wn + min(max(xx, 0), Wn - 1);
        tw.x = v ? (1.f - ly) * (1.f - lx) * m : 0.f;
    }
    {
        int yy = y0, xx = x0 + 1;
        bool v = (yy >= 0) && (yy < Hn) && (xx >= 0) && (xx < Wn);
        ti.y = min(max(yy, 0), Hn - 1) * Wn + min(max(xx, 0), Wn - 1);
        tw.y = v ? (1.f - ly) * lx * m : 0.f;
    }
    {
        int yy = y0 + 1, xx = x0;
        bool v = (yy >= 0) && (yy < Hn) && (xx >= 0) && (xx < Wn);
        ti.z = min(max(yy, 0), Hn - 1) * Wn + min(max(xx, 0), Wn - 1);
        tw.z = v ? ly * (1.f - lx) * m : 0.f;
    }
    {
        int yy = y0 + 1, xx = x0 + 1;
        bool v = (yy >= 0) && (yy < Hn) && (xx >= 0) && (xx < Wn);
        ti.w = min(max(yy, 0), Hn - 1) * Wn + min(max(xx, 0), Wn - 1);
        tw.w = v ? ly * lx * m : 0.f;
    }
    *(int4*)(tb + col * 8) = ti;
    *(float4*)(tb + col * 8 + 4) = tw;
}

// gather -> fp16 combine -> store one position's 64 channels for this quarter-thread
__device__ __forceinline__ void b_combine_store(char* bd, const uint4* u, float4 twr, int gu) {
#pragma unroll
    for (int item = 0; item < 2; item++) {
        float r[8] = {0, 0, 0, 0, 0, 0, 0, 0};
#pragma unroll
        for (int tp4 = 0; tp4 < 4; tp4++) {
            uint4 q = u[tp4 * 2 + item];
            float wt = (tp4 == 0) ? twr.x : (tp4 == 1) ? twr.y : (tp4 == 2) ? twr.z : twr.w;
            const __half2* hh = (const __half2*)&q;
#pragma unroll
            for (int e = 0; e < 4; e++) {
                float2 f = __half22float2(hh[e]);
                r[e * 2] = fmaf(wt, f.x, r[e * 2]);
                r[e * 2 + 1] = fmaf(wt, f.y, r[e * 2 + 1]);
            }
        }
        __half2 o0 = __floats2half2_rn(r[0], r[1]), o1 = __floats2half2_rn(r[2], r[3]);
        __half2 o2 = __floats2half2_rn(r[4], r[5]), o3 = __floats2half2_rn(r[6], r[7]);
        uint4 ov = make_uint4(*(uint32_t*)&o0, *(uint32_t*)&o1, *(uint32_t*)&o2, *(uint32_t*)&o3);
        *(uint4*)(bd + (gu + item * 4) * 16) = ov;
    }
}

__device__ __forceinline__ void gather_loads(const __half* xg, int4 ti, uint4* u) {
    u[0] = __ldg((const uint4*)(xg + (size_t)ti.x * Cn));
    u[1] = __ldg((const uint4*)(xg + (size_t)ti.x * Cn + 32));
    u[2] = __ldg((const uint4*)(xg + (size_t)ti.y * Cn));
    u[3] = __ldg((const uint4*)(xg + (size_t)ti.y * Cn + 32));
    u[4] = __ldg((const uint4*)(xg + (size_t)ti.z * Cn));
    u[5] = __ldg((const uint4*)(xg + (size_t)ti.z * Cn + 32));
    u[6] = __ldg((const uint4*)(xg + (size_t)ti.w * Cn));
    u[7] = __ldg((const uint4*)(xg + (size_t)ti.w * Cn + 32));
}

// ---------------- kernel: deformable gather + fp16 2-term HMMA ----------------
// 256 threads = 8 warps (mw 0..3 x nw 0..1). Warp tile M=32 x N=32.
// CTA: 1 output row (64 pos) x 128 out-ch. No reg prefetch; 3 CTAs/SM for TLP.
__global__ __launch_bounds__(256, 3) void k_main_mma(float* __restrict__ out)
{
    extern __shared__ __align__(16) char smem[];
    const int t = threadIdx.x, w = t >> 5, lane = t & 31;
    const int gid = lane >> 2, tig = lane & 3;
    const int mw = w & 3, nw = w >> 2;
    const int gpos = t >> 2, gu = t & 3;
    const int b = blockIdx.x >> 6, ho = blockIdx.x & 63;
    const __half* xtb = g_xt + (size_t)b * HW * Cn;
    const float* om = g_offmask + (size_t)b * 27 * HW;

    float acc[2][4][4];
#pragma unroll
    for (int mt = 0; mt < 2; mt++)
#pragma unroll
        for (int nt = 0; nt < 4; nt++)
#pragma unroll
            for (int r = 0; r < 4; r++) acc[mt][nt][r] = 0.f;

    tap_compute(om, (float*)(smem + SM_TAPS(0)), t, ho, 0);
    __syncthreads();

    for (int it = 0; it < NCH; it++) {
        const int s = it & 1;
        const int j = it >> 1, ch = it & 1;
        // fill B[s]: gather + combine + STS (current it)
        {
            const float* tp = (const float*)(smem + SM_TAPS(j & 1)) + gpos * 8;
            int4 ti = *(const int4*)tp;
            float4 twr = *(const float4*)(tp + 4);
            uint4 u[8];
            gather_loads(xtb + ch * 64 + gu * 8, ti, u);
            b_combine_store(smem + SMB(s) + gpos * BPITCH, u, twr, gu);
            // compute next j's taps during odd-it fill (double-buffered, 2 syncs from readers)
            if (ch == 1 && j < 8)
                tap_compute(om, (float*)(smem + SM_TAPS((j + 1) & 1)), t, ho, j + 1);
        }
        __syncthreads();
        // mma on B[s]; fill(it+1) targets B[s^1], so no trailing sync needed
        const char* bs = smem + SMB(s);
        const unsigned char* gA = g_Amain + (size_t)it * 32768 + (size_t)mw * 8192 + lane * 16;
#pragma unroll
        for (int kt = 0; kt < 4; kt++) {
            uint4 aH0 = __ldg((const uint4*)(gA + kt * 2048));
            uint4 aL0 = __ldg((const uint4*)(gA + kt * 2048 + 512));
            uint4 aH1 = __ldg((const uint4*)(gA + kt * 2048 + 1024));
            uint4 aL1 = __ldg((const uint4*)(gA + kt * 2048 + 1536));
#pragma unroll
            for (int nt = 0; nt < 4; nt++) {
                uint2 bv = *(const uint2*)(bs + (nw * 32 + nt * 8 + gid) * BPITCH + (kt * 4 + tig) * 8);
                mma_f16(acc[0][nt], (const uint32_t*)&aH0, bv.x, bv.y);
                mma_f16(acc[0][nt], (const uint32_t*)&aL0, bv.x, bv.y);
                mma_f16(acc[1][nt], (const uint32_t*)&aH1, bv.x, bv.y);
                mma_f16(acc[1][nt], (const uint32_t*)&aL1, bv.x, bv.y);
            }
        }
    }
    __syncthreads();

    // epilogue: two halves of 64 output channels, staged via smem (pitch 68 floats = 272B, 16B-aligned)
    float* ob = out + (size_t)b * On * HW + (size_t)ho * Wn;
    float* stage = (float*)smem;   // 64 rows x 68 floats = 17.4KB
#pragma unroll
    for (int half = 0; half < 2; half++) {
        if ((mw >> 1) == half) {
            int rbase = (mw & 1) * 32 + gid;
#pragma unroll
            for (int mt = 0; mt < 2; mt++)
#pragma unroll
                for (int nt = 0; nt < 4; nt++) {
                    int p0 = nw * 32 + nt * 8 + 2 * tig;
                    *(float2*)(stage + (rbase + mt * 16) * 68 + p0) =
                        make_float2(acc[mt][nt][0], acc[mt][nt][1]);
                    *(float2*)(stage + (rbase + mt * 16 + 8) * 68 + p0) =
                        make_float2(acc[mt][nt][2], acc[mt][nt][3]);
                }
        }
        __syncthreads();
#pragma unroll
        for (int e = t; e < 1024; e += 256) {
            int o = e >> 4, q = e & 15;
            float4 v = *(float4*)(stage + o * 68 + q * 4);
            *(float4*)(ob + (size_t)(half * 64 + o) * HW + q * 4) = v;
        }
        __syncthreads();
    }
}

// ---------------- launch ----------------
extern "C" void kernel_launch(void* const* d_in, const int* in_sizes, int n_in,
                              void* d_out, int out_size) {
    const float* x      = (const float*)d_in[0];
    const float* w_off  = (const float*)d_in[1];
    const float* b_off  = (const float*)d_in[2];
    const float* w_msk  = (const float*)d_in[3];
    const float* b_msk  = (const float*)d_in[4];
    const float* weight = (const float*)d_in[5];
    float* out = (float*)d_out;

    dim3 gxt(HW / 32, Cn / 32, Bn);
    k_xt<<<gxt, dim3(32, 8)>>>(x);
    k_prep<<<(18432 + 4608 + 255) / 256, 256>>>(weight, w_off, w_msk);
    k_offmask_mma<<<Bn * 32, 128>>>(b_off, b_msk);
    k_main_mma<<<Bn * 64, 256, SM_TOTAL>>>(out);
}

// round 9
// speedup vs baseline: 4.8528x; 1.0864x over previous
#include <cuda_runtime.h>
#include <cuda_fp16.h>
#include <cstdint>
#include <math.h>

#define Bn 8
#define Cn 128
#define Hn 64
#define Wn 64
#define On 128
#define K2 9
#define HW 4096
#define CK 1152
#define NCH 18

// ---------------- scratch ----------------
__device__ float g_offmask[Bn * 27 * HW];
__device__ __half g_xt[Bn * HW * Cn];                  // NHWC fp16, channel-permuted per 64-block
// main A frags fp16 (hi only): [it18][mw4][kt4][mt2][lane32][16B] = 16KB/it
__device__ __align__(16) unsigned char g_Amain[NCH * 16384];
// off A frags (hi+lo): [it18][mt2][kt4][term2][lane32][16B] = 8KB/it
__device__ __align__(16) unsigned char g_Aoff[NCH * 8192];

// k_main smem (bytes): B bufs 2 x (64 pos x 160B) = 20480; taps 2 x 2048
#define BPITCH 160
#define SMB(s)    ((s) * 10240)
#define SM_TAPS(tb) (20480 + (tb) * 2048)
#define SM_TOTAL 24576

// ---------------- helpers ----------------
__device__ __forceinline__ void split2h(float v0, float v1, uint32_t& hp, uint32_t& lp) {
    __half h0 = __float2half_rn(v0), h1 = __float2half_rn(v1);
    __half l0 = __float2half_rn(v0 - __half2float(h0));
    __half l1 = __float2half_rn(v1 - __half2float(h1));
    __half2 H = __halves2half2(h0, h1);
    __half2 L = __halves2half2(l0, l1);
    hp = *(uint32_t*)&H; lp = *(uint32_t*)&L;
}
__device__ __forceinline__ uint32_t pack2h(float v0, float v1) {
    __half2 H = __floats2half2_rn(v0, v1);
    return *(uint32_t*)&H;
}
__device__ __forceinline__ void mma_f16(float* d, const uint32_t* a, uint32_t b0, uint32_t b1) {
    asm volatile(
        "mma.sync.aligned.m16n8k16.row.col.f32.f16.f16.f32 "
        "{%0,%1,%2,%3},{%4,%5,%6,%7},{%8,%9},{%0,%1,%2,%3};"
        : "+f"(d[0]), "+f"(d[1]), "+f"(d[2]), "+f"(d[3])
        : "r"(a[0]), "r"(a[1]), "r"(a[2]), "r"(a[3]), "r"(b0), "r"(b1));
}
// channel permutation within each 64-block (lc even)
__device__ __forceinline__ int permq(int lc) {
    int kt = lc >> 4, k = lc & 15;
    if (k < 8) return (kt * 4 + (k >> 1)) * 4;
    return (kt * 4 + ((k - 8) >> 1)) * 4 + 2;
}

// ---------------- kernel: NCHW fp32 -> permuted NHWC fp16 ----------------
__global__ __launch_bounds__(256) void k_xt(const float* __restrict__ x) {
    __shared__ float sm[32][33];
    const int tx = threadIdx.x, ty = threadIdx.y;
    const int hw0 = blockIdx.x * 32, c0 = blockIdx.y * 32, b = blockIdx.z;
    const float* xb = x + (size_t)b * Cn * HW;
    __half* xtb = g_xt + (size_t)b * HW * Cn;
#pragma unroll
    for (int i = 0; i < 4; i++)
        sm[ty + i * 8][tx] = xb[(size_t)(c0 + ty + i * 8) * HW + hw0 + tx];
    __syncthreads();
    const int id = ty * 32 + tx;
#pragma unroll
    for (int r = 0; r < 2; r++) {
        int item = id + r * 256;
        int hwl = item >> 4, cp = item & 15;
        int c = c0 + cp * 2;
        int blk = c >> 6, lc = c & 63;
        __half2 h = __floats2half2_rn(sm[cp * 2][hwl], sm[cp * 2 + 1][hwl]);
        *(__half2*)(xtb + (size_t)(hw0 + hwl) * Cn + blk * 64 + permq(lc)) = h;
    }
}

// ---------------- kernel: weight prep ----------------
__global__ void k_prep(const float* __restrict__ wmain,
                       const float* __restrict__ woff,
                       const float* __restrict__ wmsk) {
    int i = blockIdx.x * 256 + threadIdx.x;
    if (i < 18432) {
        int lane = i & 31, mt = (i >> 5) & 1, kt = (i >> 6) & 3, mw = (i >> 8) & 3, it = i >> 10;
        int gid = lane >> 2, tig = lane & 3;
        int j = it >> 1, ch = it & 1;
        int r0 = mw * 32 + mt * 16 + gid;
        int cb = ch * 64 + kt * 16 + tig * 2;
        float wv[2][4];
#pragma unroll
        for (int rr = 0; rr < 2; rr++) {
            int r = r0 + rr * 8;
#pragma unroll
            for (int cc = 0; cc < 4; cc++) {
                int c = cb + (cc >> 1) * 8 + (cc & 1);
                wv[rr][cc] = wmain[(size_t)r * CK + c * K2 + j];
            }
        }
        uint4 hi;
        hi.x = pack2h(wv[0][0], wv[0][1]);
        hi.y = pack2h(wv[1][0], wv[1][1]);
        hi.z = pack2h(wv[0][2], wv[0][3]);
        hi.w = pack2h(wv[1][2], wv[1][3]);
        size_t base = (size_t)it * 16384 + (size_t)((mw * 4 + kt) * 2 + mt) * 512 + lane * 16;
        *(uint4*)(g_Amain + base) = hi;
    } else if (i < 18432 + 4608) {
        int q = i - 18432;
        int lane = q & 31, kt = (q >> 5) & 3, mt = (q >> 7) & 1, it = q >> 8;
        int gid = lane >> 2, tig = lane & 3;
        int j = it >> 1, ch = it & 1;
        int r0 = mt * 16 + gid;
        int cb = ch * 64 + kt * 16 + tig * 2;
        float wv[2][4];
#pragma unroll
        for (int rr = 0; rr < 2; rr++) {
            int r = r0 + rr * 8;
#pragma unroll
            for (int cc = 0; cc < 4; cc++) {
                int c = cb + (cc >> 1) * 8 + (cc & 1);
                float v = 0.f;
                if (r < 18)      v = woff[(size_t)r * CK + c * K2 + j];
                else if (r < 27) v = wmsk[(size_t)(r - 18) * CK + c * K2 + j];
                wv[rr][cc] = v;
            }
        }
        uint4 hi, lo; uint32_t hp, lp;
        split2h(wv[0][0], wv[0][1], hp, lp); hi.x = hp; lo.x = lp;
        split2h(wv[1][0], wv[1][1], hp, lp); hi.y = hp; lo.y = lp;
        split2h(wv[0][2], wv[0][3], hp, lp); hi.z = hp; lo.z = lp;
        split2h(wv[1][2], wv[1][3], hp, lp); hi.w = hp; lo.w = lp;
        size_t base = (size_t)it * 8192 + (size_t)(mt * 4 + kt) * 1024 + lane * 16;
        *(uint4*)(g_Aoff + base) = hi;
        *(uint4*)(g_Aoff + base + 512) = lo;
    }
}

// ---------------- kernel: offset+mask conv (fp16 2-term HMMA) ----------------
// 128 threads = 4 warps, warp tile M=32 x N=32. CTA covers 128 pos (2 rows).
__global__ __launch_bounds__(128) void k_offmask_mma(
    const float* __restrict__ b_off, const float* __restrict__ b_msk)
{
    const int t = threadIdx.x, w = t >> 5, lane = t & 31;
    const int gid = lane >> 2, tig = lane & 3;
    const int b = blockIdx.x >> 5, rp = blockIdx.x & 31, ho0 = rp * 2;
    const __half* xtb = g_xt + (size_t)b * HW * Cn;

    float acc[2][4][4];
#pragma unroll
    for (int mt = 0; mt < 2; mt++)
#pragma unroll
        for (int nt = 0; nt < 4; nt++)
#pragma unroll
            for (int r = 0; r < 4; r++) acc[mt][nt][r] = 0.f;

    for (int it = 0; it < NCH; it++) {
        const int j = it >> 1, ch = it & 1;
        const int jy = j / 3, jx = j - jy * 3;
        uint4 aH[2][4], aL[2][4];
        {
            const unsigned char* gb = g_Aoff + (size_t)it * 8192 + lane * 16;
#pragma unroll
            for (int mt = 0; mt < 2; mt++)
#pragma unroll
                for (int kt = 0; kt < 4; kt++) {
                    size_t o = (size_t)(mt * 4 + kt) * 1024;
                    aH[mt][kt] = __ldg((const uint4*)(gb + o));
                    aL[mt][kt] = __ldg((const uint4*)(gb + o + 512));
                }
        }
#pragma unroll
        for (int nt = 0; nt < 4; nt++) {
            int pos = w * 32 + nt * 8 + gid;
            int row = ho0 + (pos >> 6), col = pos & 63;
            int sy = row + jy - 1, sx = col + jx - 1;
            bool valid = ((unsigned)sy < Hn) && ((unsigned)sx < Wn);
            const char* src = (const char*)(xtb + (size_t)(valid ? sy * Wn + sx : 0) * Cn + ch * 64);
#pragma unroll
            for (int kt = 0; kt < 4; kt++) {
                uint2 bv = make_uint2(0u, 0u);
                if (valid) bv = *(const uint2*)(src + (kt * 4 + tig) * 8);
#pragma unroll
                for (int mt = 0; mt < 2; mt++) {
                    mma_f16(acc[mt][nt], (const uint32_t*)&aH[mt][kt], bv.x, bv.y);
                    mma_f16(acc[mt][nt], (const uint32_t*)&aL[mt][kt], bv.x, bv.y);
                }
            }
        }
    }
    float* om = g_offmask + (size_t)b * 27 * HW;
#pragma unroll
    for (int mt = 0; mt < 2; mt++)
#pragma unroll
        for (int rr = 0; rr < 2; rr++) {
            int o = mt * 16 + gid + rr * 8;
            if (o >= 27) continue;
            float bias = (o < 18) ? __ldg(b_off + o) : __ldg(b_msk + o - 18);
#pragma unroll
            for (int nt = 0; nt < 4; nt++) {
                int pos = w * 32 + nt * 8 + 2 * tig;
                int gp = (ho0 + (pos >> 6)) * Wn + (pos & 63);
                float v0 = acc[mt][nt][rr * 2 + 0] + bias;
                float v1 = acc[mt][nt][rr * 2 + 1] + bias;
                if (o >= 18) {
                    v0 = 1.f / (1.f + __expf(-v0));
                    v1 = 1.f / (1.f + __expf(-v1));
                }
                *(float2*)(om + (size_t)o * HW + gp) = make_float2(v0, v1);
            }
        }
}

// ---------------- k_main: tap compute (64 pos, one row) ----------------
__device__ __forceinline__ void tap_compute(const float* __restrict__ om, float* tb,
                                            int t, int ho, int j) {
    if (t >= 64) return;
    int col = t;
    int gp = ho * Wn + col;
    int jy = j / 3, jx = j - jy * 3;
    float dy = __ldg(om + (size_t)(2 * j) * HW + gp);
    float dx = __ldg(om + (size_t)(2 * j + 1) * HW + gp);
    float m  = __ldg(om + (size_t)(18 + j) * HW + gp);
    float py = dy + (float)(jy + ho - 1);
    float px = dx + (float)(jx + col - 1);
    float y0f = floorf(py), x0f = floorf(px);
    float ly = py - y0f, lx = px - x0f;
    int y0 = (int)y0f, x0 = (int)x0f;
    int4 ti; float4 tw;
    {
        int yy = y0, xx = x0;
        bool v = (yy >= 0) && (yy < Hn) && (xx >= 0) && (xx < Wn);
        ti.x = min(max(yy, 0), Hn - 1) * Wn + min(max(xx, 0), Wn - 1);
        tw.x = v ? (1.f - ly) * (1.f - lx) * m : 0.f;
    }
    {
        int yy = y0, xx = x0 + 1;
        bool v = (yy >= 0) && (yy < Hn) && (xx >= 0) && (xx < Wn);
        ti.y = min(max(yy, 0), Hn - 1) * Wn + min(max(xx, 0), Wn - 1);
        tw.y = v ? (1.f - ly) * lx * m : 0.f;
    }
    {
        int yy = y0 + 1, xx = x0;
        bool v = (yy >= 0) && (yy < Hn) && (xx >= 0) && (xx < Wn);
        ti.z = min(max(yy, 0), Hn - 1) * Wn + min(max(xx, 0), Wn - 1);
        tw.z = v ? ly * (1.f - lx) * m : 0.f;
    }
    {
        int yy = y0 + 1, xx = x0 + 1;
        bool v = (yy >= 0) && (yy < Hn) && (xx >= 0) && (xx < Wn);
        ti.w = min(max(yy, 0), Hn - 1) * Wn + min(max(xx, 0), Wn - 1);
        tw.w = v ? ly * lx * m : 0.f;
    }
    *(int4*)(tb + col * 8) = ti;
    *(float4*)(tb + col * 8 + 4) = tw;
}

// gather -> fp16 combine -> store one position's 64 channels for this quarter-thread
__device__ __forceinline__ void b_combine_store(char* bd, const uint4* u, float4 twr, int gu) {
#pragma unroll
    for (int item = 0; item < 2; item++) {
        float r[8] = {0, 0, 0, 0, 0, 0, 0, 0};
#pragma unroll
        for (int tp4 = 0; tp4 < 4; tp4++) {
            uint4 q = u[tp4 * 2 + item];
            float wt = (tp4 == 0) ? twr.x : (tp4 == 1) ? twr.y : (tp4 == 2) ? twr.z : twr.w;
            const __half2* hh = (const __half2*)&q;
#pragma unroll
            for (int e = 0; e < 4; e++) {
                float2 f = __half22float2(hh[e]);
                r[e * 2] = fmaf(wt, f.x, r[e * 2]);
                r[e * 2 + 1] = fmaf(wt, f.y, r[e * 2 + 1]);
            }
        }
        __half2 o0 = __floats2half2_rn(r[0], r[1]), o1 = __floats2half2_rn(r[2], r[3]);
        __half2 o2 = __floats2half2_rn(r[4], r[5]), o3 = __floats2half2_rn(r[6], r[7]);
        uint4 ov = make_uint4(*(uint32_t*)&o0, *(uint32_t*)&o1, *(uint32_t*)&o2, *(uint32_t*)&o3);
        *(uint4*)(bd + (gu + item * 4) * 16) = ov;
    }
}

__device__ __forceinline__ void gather_loads(const __half* xg, int4 ti, uint4* u) {
    u[0] = __ldg((const uint4*)(xg + (size_t)ti.x * Cn));
    u[1] = __ldg((const uint4*)(xg + (size_t)ti.x * Cn + 32));
    u[2] = __ldg((const uint4*)(xg + (size_t)ti.y * Cn));
    u[3] = __ldg((const uint4*)(xg + (size_t)ti.y * Cn + 32));
    u[4] = __ldg((const uint4*)(xg + (size_t)ti.z * Cn));
    u[5] = __ldg((const uint4*)(xg + (size_t)ti.z * Cn + 32));
    u[6] = __ldg((const uint4*)(xg + (size_t)ti.w * Cn));
    u[7] = __ldg((const uint4*)(xg + (size_t)ti.w * Cn + 32));
}

// ---------------- kernel: deformable gather + fp16 1-term HMMA ----------------
// 256 threads = 8 warps (mw 0..3 x nw 0..1). Warp tile M=32 x N=32. 3 CTAs/SM.
__global__ __launch_bounds__(256, 3) void k_main_mma(float* __restrict__ out)
{
    extern __shared__ __align__(16) char smem[];
    const int t = threadIdx.x, w = t >> 5, lane = t & 31;
    const int gid = lane >> 2, tig = lane & 3;
    const int mw = w & 3, nw = w >> 2;
    const int gpos = t >> 2, gu = t & 3;
    const int b = blockIdx.x >> 6, ho = blockIdx.x & 63;
    const __half* xtb = g_xt + (size_t)b * HW * Cn;
    const float* om = g_offmask + (size_t)b * 27 * HW;

    float acc[2][4][4];
#pragma unroll
    for (int mt = 0; mt < 2; mt++)
#pragma unroll
        for (int nt = 0; nt < 4; nt++)
#pragma unroll
            for (int r = 0; r < 4; r++) acc[mt][nt][r] = 0.f;

    tap_compute(om, (float*)(smem + SM_TAPS(0)), t, ho, 0);
    __syncthreads();

    for (int it = 0; it < NCH; it++) {
        const int s = it & 1;
        const int j = it >> 1, ch = it & 1;
        // fill B[s]: gather + combine + STS (current it)
        {
            const float* tp = (const float*)(smem + SM_TAPS(j & 1)) + gpos * 8;
            int4 ti = *(const int4*)tp;
            float4 twr = *(const float4*)(tp + 4);
            uint4 u[8];
            gather_loads(xtb + ch * 64 + gu * 8, ti, u);
            b_combine_store(smem + SMB(s) + gpos * BPITCH, u, twr, gu);
            // compute next j's taps during odd-it fill (double-buffered, 2 syncs from readers)
            if (ch == 1 && j < 8)
                tap_compute(om, (float*)(smem + SM_TAPS((j + 1) & 1)), t, ho, j + 1);
        }
        __syncthreads();
        // mma on B[s]; fill(it+1) targets B[s^1], so no trailing sync needed
        const char* bs = smem + SMB(s);
        const unsigned char* gA = g_Amain + (size_t)it * 16384 + (size_t)mw * 4096 + lane * 16;
#pragma unroll
        for (int kt = 0; kt < 4; kt++) {
            uint4 aH0 = __ldg((const uint4*)(gA + kt * 1024));
            uint4 aH1 = __ldg((const uint4*)(gA + kt * 1024 + 512));
#pragma unroll
            for (int nt = 0; nt < 4; nt++) {
                uint2 bv = *(const uint2*)(bs + (nw * 32 + nt * 8 + gid) * BPITCH + (kt * 4 + tig) * 8);
                mma_f16(acc[0][nt], (const uint32_t*)&aH0, bv.x, bv.y);
                mma_f16(acc[1][nt], (const uint32_t*)&aH1, bv.x, bv.y);
            }
        }
    }
    __syncthreads();

    // epilogue: two halves of 64 output channels, staged via smem (pitch 68 floats = 272B, 16B-aligned)
    float* ob = out + (size_t)b * On * HW + (size_t)ho * Wn;
    float* stage = (float*)smem;   // 64 rows x 68 floats = 17.4KB
#pragma unroll
    for (int half = 0; half < 2; half++) {
        if ((mw >> 1) == half) {
            int rbase = (mw & 1) * 32 + gid;
#pragma unroll
            for (int mt = 0; mt < 2; mt++)
#pragma unroll
                for (int nt = 0; nt < 4; nt++) {
                    int p0 = nw * 32 + nt * 8 + 2 * tig;
                    *(float2*)(stage + (rbase + mt * 16) * 68 + p0) =
                        make_float2(acc[mt][nt][0], acc[mt][nt][1]);
                    *(float2*)(stage + (rbase + mt * 16 + 8) * 68 + p0) =
                        make_float2(acc[mt][nt][2], acc[mt][nt][3]);
                }
        }
        __syncthreads();
#pragma unroll
        for (int e = t; e < 1024; e += 256) {
            int o = e >> 4, q = e & 15;
            float4 v = *(float4*)(stage + o * 68 + q * 4);
            *(float4*)(ob + (size_t)(half * 64 + o) * HW + q * 4) = v;
        }
        __syncthreads();
    }
}

// ---------------- launch ----------------
extern "C" void kernel_launch(void* const* d_in, const int* in_sizes, int n_in,
                              void* d_out, int out_size) {
    const float* x      = (const float*)d_in[0];
    const float* w_off  = (const float*)d_in[1];
    const float* b_off  = (const float*)d_in[2];
    const float* w_msk  = (const float*)d_in[3];
    const float* b_msk  = (const float*)d_in[4];
    const float* weight = (const float*)d_in[5];
    float* out = (float*)d_out;

    dim3 gxt(HW / 32, Cn / 32, Bn);
    k_xt<<<gxt, dim3(32, 8)>>>(x);
    k_prep<<<(18432 + 4608 + 255) / 256, 256>>>(weight, w_off, w_msk);
    k_offmask_mma<<<Bn * 32, 128>>>(b_off, b_msk);
    k_main_mma<<<Bn * 64, 256, SM_TOTAL>>>(out);
}

// round 10
// speedup vs baseline: 5.2574x; 1.0834x over previous
#include <cuda_runtime.h>
#include <cuda_fp16.h>
#include <cstdint>
#include <math.h>

#define Bn 8
#define Cn 128
#define Hn 64
#define Wn 64
#define On 128
#define K2 9
#define HW 4096
#define CK 1152
#define NCH 18

// ---------------- scratch ----------------
__device__ float g_offmask[Bn * 27 * HW];
__device__ __half g_xt[Bn * HW * Cn];                  // NHWC fp16, channel-permuted per 64-block
// main A frags fp16 (hi only): [it18][mw4][kt4][mt2][lane32][16B] = 16KB/it
__device__ __align__(16) unsigned char g_Amain[NCH * 16384];
// off A frags (hi only): [it18][mt2][kt4][lane32][16B] = 4KB/it
__device__ __align__(16) unsigned char g_Aoff[NCH * 4096];

// k_main smem (bytes): B bufs 2 x (64 pos x 160B) = 20480; taps 2 x 2048
#define BPITCH 160
#define SMB(s)    ((s) * 10240)
#define SM_TAPS(tb) (20480 + (tb) * 2048)
#define SM_TOTAL 24576

// ---------------- helpers ----------------
__device__ __forceinline__ uint32_t pack2h(float v0, float v1) {
    __half2 H = __floats2half2_rn(v0, v1);
    return *(uint32_t*)&H;
}
__device__ __forceinline__ void mma_f16(float* d, const uint32_t* a, uint32_t b0, uint32_t b1) {
    asm volatile(
        "mma.sync.aligned.m16n8k16.row.col.f32.f16.f16.f32 "
        "{%0,%1,%2,%3},{%4,%5,%6,%7},{%8,%9},{%0,%1,%2,%3};"
        : "+f"(d[0]), "+f"(d[1]), "+f"(d[2]), "+f"(d[3])
        : "r"(a[0]), "r"(a[1]), "r"(a[2]), "r"(a[3]), "r"(b0), "r"(b1));
}
// channel permutation within each 64-block (lc even)
__device__ __forceinline__ int permq(int lc) {
    int kt = lc >> 4, k = lc & 15;
    if (k < 8) return (kt * 4 + (k >> 1)) * 4;
    return (kt * 4 + ((k - 8) >> 1)) * 4 + 2;
}

// ---------------- kernel: NCHW fp32 -> permuted NHWC fp16 ----------------
__global__ __launch_bounds__(256) void k_xt(const float* __restrict__ x) {
    __shared__ float sm[32][33];
    const int tx = threadIdx.x, ty = threadIdx.y;
    const int hw0 = blockIdx.x * 32, c0 = blockIdx.y * 32, b = blockIdx.z;
    const float* xb = x + (size_t)b * Cn * HW;
    __half* xtb = g_xt + (size_t)b * HW * Cn;
#pragma unroll
    for (int i = 0; i < 4; i++)
        sm[ty + i * 8][tx] = xb[(size_t)(c0 + ty + i * 8) * HW + hw0 + tx];
    __syncthreads();
    const int id = ty * 32 + tx;
#pragma unroll
    for (int r = 0; r < 2; r++) {
        int item = id + r * 256;
        int hwl = item >> 4, cp = item & 15;
        int c = c0 + cp * 2;
        int blk = c >> 6, lc = c & 63;
        __half2 h = __floats2half2_rn(sm[cp * 2][hwl], sm[cp * 2 + 1][hwl]);
        *(__half2*)(xtb + (size_t)(hw0 + hwl) * Cn + blk * 64 + permq(lc)) = h;
    }
}

// ---------------- kernel: weight prep (fp16 hi fragments) ----------------
__global__ void k_prep(const float* __restrict__ wmain,
                       const float* __restrict__ woff,
                       const float* __restrict__ wmsk) {
    int i = blockIdx.x * 256 + threadIdx.x;
    if (i < 18432) {
        int lane = i & 31, mt = (i >> 5) & 1, kt = (i >> 6) & 3, mw = (i >> 8) & 3, it = i >> 10;
        int gid = lane >> 2, tig = lane & 3;
        int j = it >> 1, ch = it & 1;
        int r0 = mw * 32 + mt * 16 + gid;
        int cb = ch * 64 + kt * 16 + tig * 2;
        float wv[2][4];
#pragma unroll
        for (int rr = 0; rr < 2; rr++) {
            int r = r0 + rr * 8;
#pragma unroll
            for (int cc = 0; cc < 4; cc++) {
                int c = cb + (cc >> 1) * 8 + (cc & 1);
                wv[rr][cc] = wmain[(size_t)r * CK + c * K2 + j];
            }
        }
        uint4 hi;
        hi.x = pack2h(wv[0][0], wv[0][1]);
        hi.y = pack2h(wv[1][0], wv[1][1]);
        hi.z = pack2h(wv[0][2], wv[0][3]);
        hi.w = pack2h(wv[1][2], wv[1][3]);
        size_t base = (size_t)it * 16384 + (size_t)((mw * 4 + kt) * 2 + mt) * 512 + lane * 16;
        *(uint4*)(g_Amain + base) = hi;
    } else if (i < 18432 + 4608) {
        int q = i - 18432;
        int lane = q & 31, kt = (q >> 5) & 3, mt = (q >> 7) & 1, it = q >> 8;
        int gid = lane >> 2, tig = lane & 3;
        int j = it >> 1, ch = it & 1;
        int r0 = mt * 16 + gid;
        int cb = ch * 64 + kt * 16 + tig * 2;
        float wv[2][4];
#pragma unroll
        for (int rr = 0; rr < 2; rr++) {
            int r = r0 + rr * 8;
#pragma unroll
            for (int cc = 0; cc < 4; cc++) {
                int c = cb + (cc >> 1) * 8 + (cc & 1);
                float v = 0.f;
                if (r < 18)      v = woff[(size_t)r * CK + c * K2 + j];
                else if (r < 27) v = wmsk[(size_t)(r - 18) * CK + c * K2 + j];
                wv[rr][cc] = v;
            }
        }
        uint4 hi;
        hi.x = pack2h(wv[0][0], wv[0][1]);
        hi.y = pack2h(wv[1][0], wv[1][1]);
        hi.z = pack2h(wv[0][2], wv[0][3]);
        hi.w = pack2h(wv[1][2], wv[1][3]);
        size_t base = (size_t)it * 4096 + (size_t)(mt * 4 + kt) * 512 + lane * 16;
        *(uint4*)(g_Aoff + base) = hi;
    }
}

// ---------------- kernel: offset+mask conv (fp16 1-term HMMA) ----------------
// 128 threads = 4 warps; warp w covers row ho0+w (64 pos), tile M=32 x N=64.
__global__ __launch_bounds__(128) void k_offmask_mma(
    const float* __restrict__ b_off, const float* __restrict__ b_msk)
{
    const int t = threadIdx.x, w = t >> 5, lane = t & 31;
    const int gid = lane >> 2, tig = lane & 3;
    const int b = blockIdx.x >> 4, rp = blockIdx.x & 15, ho0 = rp * 4;
    const int row = ho0 + w;
    const __half* xtb = g_xt + (size_t)b * HW * Cn;

    float acc[2][8][4];
#pragma unroll
    for (int mt = 0; mt < 2; mt++)
#pragma unroll
        for (int nt = 0; nt < 8; nt++)
#pragma unroll
            for (int r = 0; r < 4; r++) acc[mt][nt][r] = 0.f;

    for (int it = 0; it < NCH; it++) {
        const int j = it >> 1, ch = it & 1;
        const int jy = j / 3, jx = j - jy * 3;
        uint4 aH[2][4];
        {
            const unsigned char* gb = g_Aoff + (size_t)it * 4096 + lane * 16;
#pragma unroll
            for (int mt = 0; mt < 2; mt++)
#pragma unroll
                for (int kt = 0; kt < 4; kt++)
                    aH[mt][kt] = __ldg((const uint4*)(gb + (size_t)(mt * 4 + kt) * 512));
        }
        const int sy = row + jy - 1;
        const bool rowok = ((unsigned)sy < Hn);
#pragma unroll
        for (int nt = 0; nt < 8; nt++) {
            int col = nt * 8 + gid;
            int sx = col + jx - 1;
            bool valid = rowok && ((unsigned)sx < Wn);
            const char* src = (const char*)(xtb + (size_t)(valid ? sy * Wn + sx : 0) * Cn + ch * 64);
#pragma unroll
            for (int kt = 0; kt < 4; kt++) {
                uint2 bv = make_uint2(0u, 0u);
                if (valid) bv = *(const uint2*)(src + (kt * 4 + tig) * 8);
#pragma unroll
                for (int mt = 0; mt < 2; mt++)
                    mma_f16(acc[mt][nt], (const uint32_t*)&aH[mt][kt], bv.x, bv.y);
            }
        }
    }
    float* om = g_offmask + (size_t)b * 27 * HW;
#pragma unroll
    for (int mt = 0; mt < 2; mt++)
#pragma unroll
        for (int rr = 0; rr < 2; rr++) {
            int o = mt * 16 + gid + rr * 8;
            if (o >= 27) continue;
            float bias = (o < 18) ? __ldg(b_off + o) : __ldg(b_msk + o - 18);
#pragma unroll
            for (int nt = 0; nt < 8; nt++) {
                int col = nt * 8 + 2 * tig;
                int gp = row * Wn + col;
                float v0 = acc[mt][nt][rr * 2 + 0] + bias;
                float v1 = acc[mt][nt][rr * 2 + 1] + bias;
                if (o >= 18) {
                    v0 = 1.f / (1.f + __expf(-v0));
                    v1 = 1.f / (1.f + __expf(-v1));
                }
                *(float2*)(om + (size_t)o * HW + gp) = make_float2(v0, v1);
            }
        }
}

// ---------------- k_main: tap compute (64 pos, one row) ----------------
__device__ __forceinline__ void tap_compute(const float* __restrict__ om, float* tb,
                                            int t, int ho, int j) {
    if (t >= 64) return;
    int col = t;
    int gp = ho * Wn + col;
    int jy = j / 3, jx = j - jy * 3;
    float dy = __ldg(om + (size_t)(2 * j) * HW + gp);
    float dx = __ldg(om + (size_t)(2 * j + 1) * HW + gp);
    float m  = __ldg(om + (size_t)(18 + j) * HW + gp);
    float py = dy + (float)(jy + ho - 1);
    float px = dx + (float)(jx + col - 1);
    float y0f = floorf(py), x0f = floorf(px);
    float ly = py - y0f, lx = px - x0f;
    int y0 = (int)y0f, x0 = (int)x0f;
    int4 ti; float4 tw;
    {
        int yy = y0, xx = x0;
        bool v = (yy >= 0) && (yy < Hn) && (xx >= 0) && (xx < Wn);
        ti.x = min(max(yy, 0), Hn - 1) * Wn + min(max(xx, 0), Wn - 1);
        tw.x = v ? (1.f - ly) * (1.f - lx) * m : 0.f;
    }
    {
        int yy = y0, xx = x0 + 1;
        bool v = (yy >= 0) && (yy < Hn) && (xx >= 0) && (xx < Wn);
        ti.y = min(max(yy, 0), Hn - 1) * Wn + min(max(xx, 0), Wn - 1);
        tw.y = v ? (1.f - ly) * lx * m : 0.f;
    }
    {
        int yy = y0 + 1, xx = x0;
        bool v = (yy >= 0) && (yy < Hn) && (xx >= 0) && (xx < Wn);
        ti.z = min(max(yy, 0), Hn - 1) * Wn + min(max(xx, 0), Wn - 1);
        tw.z = v ? ly * (1.f - lx) * m : 0.f;
    }
    {
        int yy = y0 + 1, xx = x0 + 1;
        bool v = (yy >= 0) && (yy < Hn) && (xx >= 0) && (xx < Wn);
        ti.w = min(max(yy, 0), Hn - 1) * Wn + min(max(xx, 0), Wn - 1);
        tw.w = v ? ly * lx * m : 0.f;
    }
    *(int4*)(tb + col * 8) = ti;
    *(float4*)(tb + col * 8 + 4) = tw;
}

// gather -> fp16 combine -> store one position's 64 channels for this quarter-thread
__device__ __forceinline__ void b_combine_store(char* bd, const uint4* u, float4 twr, int gu) {
#pragma unroll
    for (int item = 0; item < 2; item++) {
        float r[8] = {0, 0, 0, 0, 0, 0, 0, 0};
#pragma unroll
        for (int tp4 = 0; tp4 < 4; tp4++) {
            uint4 q = u[tp4 * 2 + item];
            float wt = (tp4 == 0) ? twr.x : (tp4 == 1) ? twr.y : (tp4 == 2) ? twr.z : twr.w;
            const __half2* hh = (const __half2*)&q;
#pragma unroll
            for (int e = 0; e < 4; e++) {
                float2 f = __half22float2(hh[e]);
                r[e * 2] = fmaf(wt, f.x, r[e * 2]);
                r[e * 2 + 1] = fmaf(wt, f.y, r[e * 2 + 1]);
            }
        }
        __half2 o0 = __floats2half2_rn(r[0], r[1]), o1 = __floats2half2_rn(r[2], r[3]);
        __half2 o2 = __floats2half2_rn(r[4], r[5]), o3 = __floats2half2_rn(r[6], r[7]);
        uint4 ov = make_uint4(*(uint32_t*)&o0, *(uint32_t*)&o1, *(uint32_t*)&o2, *(uint32_t*)&o3);
        *(uint4*)(bd + (gu + item * 4) * 16) = ov;
    }
}

__device__ __forceinline__ void gather_loads(const __half* xg, int4 ti, uint4* u) {
    u[0] = __ldg((const uint4*)(xg + (size_t)ti.x * Cn));
    u[1] = __ldg((const uint4*)(xg + (size_t)ti.x * Cn + 32));
    u[2] = __ldg((const uint4*)(xg + (size_t)ti.y * Cn));
    u[3] = __ldg((const uint4*)(xg + (size_t)ti.y * Cn + 32));
    u[4] = __ldg((const uint4*)(xg + (size_t)ti.z * Cn));
    u[5] = __ldg((const uint4*)(xg + (size_t)ti.z * Cn + 32));
    u[6] = __ldg((const uint4*)(xg + (size_t)ti.w * Cn));
    u[7] = __ldg((const uint4*)(xg + (size_t)ti.w * Cn + 32));
}

// ---------------- kernel: deformable gather + fp16 1-term HMMA ----------------
// 256 threads = 8 warps (mw 0..3 x nw 0..1). Warp tile M=32 x N=32. 3 CTAs/SM.
__global__ __launch_bounds__(256, 3) void k_main_mma(float* __restrict__ out)
{
    extern __shared__ __align__(16) char smem[];
    const int t = threadIdx.x, w = t >> 5, lane = t & 31;
    const int gid = lane >> 2, tig = lane & 3;
    const int mw = w & 3, nw = w >> 2;
    const int gpos = t >> 2, gu = t & 3;
    const int b = blockIdx.x >> 6, ho = blockIdx.x & 63;
    const __half* xtb = g_xt + (size_t)b * HW * Cn;
    const float* om = g_offmask + (size_t)b * 27 * HW;

    float acc[2][4][4];
#pragma unroll
    for (int mt = 0; mt < 2; mt++)
#pragma unroll
        for (int nt = 0; nt < 4; nt++)
#pragma unroll
            for (int r = 0; r < 4; r++) acc[mt][nt][r] = 0.f;

    tap_compute(om, (float*)(smem + SM_TAPS(0)), t, ho, 0);
    __syncthreads();

    for (int it = 0; it < NCH; it++) {
        const int s = it & 1;
        const int j = it >> 1, ch = it & 1;
        // fill B[s]: gather + combine + STS (current it)
        {
            const float* tp = (const float*)(smem + SM_TAPS(j & 1)) + gpos * 8;
            int4 ti = *(const int4*)tp;
            float4 twr = *(const float4*)(tp + 4);
            uint4 u[8];
            gather_loads(xtb + ch * 64 + gu * 8, ti, u);
            b_combine_store(smem + SMB(s) + gpos * BPITCH, u, twr, gu);
            // compute next j's taps during odd-it fill (double-buffered, 2 syncs from readers)
            if (ch == 1 && j < 8)
                tap_compute(om, (float*)(smem + SM_TAPS((j + 1) & 1)), t, ho, j + 1);
        }
        __syncthreads();
        // mma on B[s]; fill(it+1) targets B[s^1], so no trailing sync needed
        const char* bs = smem + SMB(s);
        const unsigned char* gA = g_Amain + (size_t)it * 16384 + (size_t)mw * 4096 + lane * 16;
#pragma unroll
        for (int kt = 0; kt < 4; kt++) {
            uint4 aH0 = __ldg((const uint4*)(gA + kt * 1024));
            uint4 aH1 = __ldg((const uint4*)(gA + kt * 1024 + 512));
#pragma unroll
            for (int nt = 0; nt < 4; nt++) {
                uint2 bv = *(const uint2*)(bs + (nw * 32 + nt * 8 + gid) * BPITCH + (kt * 4 + tig) * 8);
                mma_f16(acc[0][nt], (const uint32_t*)&aH0, bv.x, bv.y);
                mma_f16(acc[1][nt], (const uint32_t*)&aH1, bv.x, bv.y);
            }
        }
    }
    __syncthreads();

    // epilogue: two halves of 64 output channels, staged via smem (pitch 68 floats = 272B, 16B-aligned)
    float* ob = out + (size_t)b * On * HW + (size_t)ho * Wn;
    float* stage = (float*)smem;   // 64 rows x 68 floats = 17.4KB
#pragma unroll
    for (int half = 0; half < 2; half++) {
        if ((mw >> 1) == half) {
            int rbase = (mw & 1) * 32 + gid;
#pragma unroll
            for (int mt = 0; mt < 2; mt++)
#pragma unroll
                for (int nt = 0; nt < 4; nt++) {
                    int p0 = nw * 32 + nt * 8 + 2 * tig;
                    *(float2*)(stage + (rbase + mt * 16) * 68 + p0) =
                        make_float2(acc[mt][nt][0], acc[mt][nt][1]);
                    *(float2*)(stage + (rbase + mt * 16 + 8) * 68 + p0) =
                        make_float2(acc[mt][nt][2], acc[mt][nt][3]);
                }
        }
        __syncthreads();
#pragma unroll
        for (int e = t; e < 1024; e += 256) {
            int o = e >> 4, q = e & 15;
            float4 v = *(float4*)(stage + o * 68 + q * 4);
            *(float4*)(ob + (size_t)(half * 64 + o) * HW + q * 4) = v;
        }
        __syncthreads();
    }
}

// ---------------- launch ----------------
extern "C" void kernel_launch(void* const* d_in, const int* in_sizes, int n_in,
                              void* d_out, int out_size) {
    const float* x      = (const float*)d_in[0];
    const float* w_off  = (const float*)d_in[1];
    const float* b_off  = (const float*)d_in[2];
    const float* w_msk  = (const float*)d_in[3];
    const float* b_msk  = (const float*)d_in[4];
    const float* weight = (const float*)d_in[5];
    float* out = (float*)d_out;

    dim3 gxt(HW / 32, Cn / 32, Bn);
    k_xt<<<gxt, dim3(32, 8)>>>(x);
    k_prep<<<(18432 + 4608 + 255) / 256, 256>>>(weight, w_off, w_msk);
    k_offmask_mma<<<Bn * 16, 128>>>(b_off, b_msk);
    k_main_mma<<<Bn * 64, 256, SM_TOTAL>>>(out);
}